// round 14
// baseline (speedup 1.0000x reference)
#include <cuda_runtime.h>
#include <cuda_bf16.h>
#include <cuda_fp16.h>
#include <cstdint>

#define NN 50000
#define EE 600000
#define NPART 196   // ceil(NN/256)

// ---------------- device scratch ----------------
__device__ __align__(16) float  g_deg[NN];
__device__ __align__(16) float  g_dinv[NN];
__device__ __align__(16) __half g_ABh[NN * 128];   // edge-MLP table (fp16)
__device__ __align__(16) __half g_xlh[NN * 128];   // conv message table (fp16)
__device__ __align__(16) unsigned g_xhi[NN * 64];  // x split hi (bf16x2)
__device__ __align__(16) unsigned g_xlo[NN * 64];  // x split lo
__device__ __align__(16) unsigned g_x1hi[NN * 64]; // conv1 output split hi
__device__ __align__(16) unsigned g_x1lo[NN * 64];
__device__ __align__(16) int    g_src[EE];
__device__ __align__(16) int    g_dst[EE];
__device__ __align__(16) int    g_cnt[NN];
__device__ __align__(16) int    g_part[256];
__device__ __align__(16) int    g_row[NN + 1];
__device__ __align__(16) int    g_cur[NN];
__device__ __align__(16) int    g_csrc[EE];
__device__ __align__(16) float  g_cw[EE];
// bf16 hi/lo weights, row-major packed bf16x2: [mat][n*64 + colpair]
__device__ __align__(16) unsigned g_Bhi[3][8192];
__device__ __align__(16) unsigned g_Blo[3][8192];

// ---------------- PTX helpers (base PTX only) ----------------
__device__ __forceinline__ void mma_bf16(float* c, const unsigned* a,
                                         unsigned b0, unsigned b1) {
    asm volatile(
        "mma.sync.aligned.m16n8k16.row.col.f32.bf16.bf16.f32 "
        "{%0,%1,%2,%3}, {%4,%5,%6,%7}, {%8,%9}, {%0,%1,%2,%3};"
        : "+f"(c[0]), "+f"(c[1]), "+f"(c[2]), "+f"(c[3])
        : "r"(a[0]), "r"(a[1]), "r"(a[2]), "r"(a[3]), "r"(b0), "r"(b1));
}
__device__ __forceinline__ uint32_t smem_u32(const void* p) {
    uint32_t a;
    asm("{ .reg .u64 t; cvta.to.shared.u64 t, %1; cvt.u32.u64 %0, t; }"
        : "=r"(a) : "l"(p));
    return a;
}
__device__ __forceinline__ void cp_async16(uint32_t dst, const void* src, int nbytes) {
    asm volatile("cp.async.cg.shared.global [%0], [%1], 16, %2;"
                 :: "r"(dst), "l"(src), "r"(nbytes) : "memory");
}
__device__ __forceinline__ void cp_commit() {
    asm volatile("cp.async.commit_group;" ::: "memory");
}
__device__ __forceinline__ void cp_wait1() {
    asm volatile("cp.async.wait_group 1;" ::: "memory");
}
// gather 4 features (uint2 = 4 halves) from a fp16 table row
__device__ __forceinline__ float4 row4(const __half* tab, int s, int f4) {
    uint2 u = *(const uint2*)&tab[(size_t)s * 128 + f4];
    float2 f01 = __half22float2(*(__half2*)&u.x);
    float2 f23 = __half22float2(*(__half2*)&u.y);
    return make_float4(f01.x, f01.y, f23.x, f23.y);
}
// split two fp32 into packed bf16x2 hi + lo
__device__ __forceinline__ void split2(float f0, float f1, unsigned& uh, unsigned& ul) {
    __nv_bfloat162 h = __floats2bfloat162_rn(f0, f1);
    __nv_bfloat162 l = __floats2bfloat162_rn(f0 - __bfloat162float(h.x),
                                             f1 - __bfloat162float(h.y));
    uh = *(unsigned*)&h;
    ul = *(unsigned*)&l;
}

// ---------------- init: zero cnt, deg=1, weights, x split ----------------
__global__ void init_misc(const float* __restrict__ x,
                          const float* __restrict__ Wp1,
                          const float* __restrict__ W1,
                          const float* __restrict__ W2) {
    if (blockIdx.x < NPART) {
        int i = blockIdx.x * 256 + threadIdx.x;
        if (i < NN) { g_cnt[i] = 0; g_deg[i] = 1.0f; }
        return;
    }
    if (blockIdx.x < NPART + 96) {
        int idx = (blockIdx.x - NPART) * 256 + threadIdx.x;   // 3*8192 pairs
        if (idx >= 3 * 8192) return;
        int m  = idx >> 13;
        int p  = idx & 8191;
        int n  = p >> 6;
        int k  = (p & 63) * 2;
        float f0, f1;
        if (m == 0) {
            f0 = (n < 64) ? Wp1[n * 256 + k]     : Wp1[(n - 64) * 256 + 128 + k];
            f1 = (n < 64) ? Wp1[n * 256 + k + 1] : Wp1[(n - 64) * 256 + 128 + k + 1];
        } else if (m == 1) { f0 = W1[n * 128 + k]; f1 = W1[n * 128 + k + 1]; }
        else               { f0 = W2[n * 128 + k]; f1 = W2[n * 128 + k + 1]; }
        split2(f0, f1, g_Bhi[m][p], g_Blo[m][p]);
        return;
    }
    // x split: NN*64 pairs
    int p = (blockIdx.x - NPART - 96) * 256 + threadIdx.x;
    if (p >= NN * 64) return;
    float2 f = *(const float2*)&x[(size_t)p * 2];
    split2(f.x, f.y, g_xhi[p], g_xlo[p]);
}

// ---------------- split-bf16 HMMA GEMM, pre-split inputs, 2-deep pipeline -----
// Yh[M,128] = fp16((Xhi+Xlo)[M,128] @ B^T).  32-row tiles.
// smem (words): A ping-pong 2*(2176+2176) | Bh 8704 | Bl 8704 = 26112 (102KB)
#define RS 68
__global__ void __launch_bounds__(256, 2)
gemm_mma(const unsigned* __restrict__ Xhi, const unsigned* __restrict__ Xlo,
         const unsigned* __restrict__ Bhi, const unsigned* __restrict__ Blo,
         __half* __restrict__ Yh, int M) {
    extern __shared__ unsigned sm[];
    unsigned* A0 = sm;               // hi at +0, lo at +2176
    unsigned* A1 = sm + 4352;
    unsigned* Bh = sm + 8704;
    unsigned* Bl = sm + 8704 + 8704;

    const int tid  = threadIdx.x;
    const int lane = tid & 31;
    const int warp = tid >> 5;
    const int wm = warp & 1;
    const int wn = warp >> 1;
    const int g  = lane >> 2;
    const int tg = lane & 3;

    const int ntiles = (M + 31) >> 5;
    const uint32_t a0b = smem_u32(A0);
    const uint32_t a1b = smem_u32(A1);

    // issue one tile's hi+lo loads into a buffer (512+512 16B chunks)
    auto issue = [&](int tile, uint32_t ab) {
        int row0 = tile << 5;
        #pragma unroll
        for (int k = 0; k < 2; k++) {
            int idx = tid + k * 256;            // 512 chunks for hi
            int r = idx >> 4, c4 = (idx & 15) * 4;
            int gr = row0 + r;
            cp_async16(ab + (r * RS + c4) * 4,
                       Xhi + (size_t)gr * 64 + c4, (gr < M) ? 16 : 0);
        }
        #pragma unroll
        for (int k = 0; k < 2; k++) {
            int idx = tid + k * 256;
            int r = idx >> 4, c4 = (idx & 15) * 4;
            int gr = row0 + r;
            cp_async16(ab + (2176 + r * RS + c4) * 4,
                       Xlo + (size_t)gr * 64 + c4, (gr < M) ? 16 : 0);
        }
        cp_commit();
    };

    int t0 = blockIdx.x;
    int t1 = t0 + gridDim.x;
    if (t0 < ntiles) issue(t0, a0b); else cp_commit();
    if (t1 < ntiles) issue(t1, a1b); else cp_commit();

    // stage weights (hi+lo)
    #pragma unroll 4
    for (int i = tid; i < 8192; i += 256) {
        int n = i >> 6, cp = i & 63;
        Bh[n * RS + cp] = Bhi[i];
        Bl[n * RS + cp] = Blo[i];
    }

    int pp = 0;
    for (int tile = t0; tile < ntiles; tile += gridDim.x) {
        cp_wait1();
        __syncthreads();     // tile's A buffer full; B staged (first iter)
        unsigned* Ab = pp ? A1 : A0;
        unsigned* Ah = Ab;
        unsigned* Al = Ab + 2176;

        float acc[4][4];
        #pragma unroll
        for (int nt = 0; nt < 4; nt++)
            #pragma unroll
            for (int q = 0; q < 4; q++) acc[nt][q] = 0.f;

        #pragma unroll
        for (int kc = 0; kc < 8; kc++) {
            unsigned ah[4], al[4];
            int w0 = (wm * 16 + g) * RS + kc * 8 + tg;
            ah[0] = Ah[w0];
            ah[1] = Ah[w0 + 8 * RS];
            ah[2] = Ah[w0 + 4];
            ah[3] = Ah[w0 + 8 * RS + 4];
            al[0] = Al[w0];
            al[1] = Al[w0 + 8 * RS];
            al[2] = Al[w0 + 4];
            al[3] = Al[w0 + 8 * RS + 4];
            #pragma unroll
            for (int nt = 0; nt < 4; nt++) {
                int nb = (wn * 32 + nt * 8 + g) * RS + kc * 8 + tg;
                unsigned bh0 = Bh[nb], bh1 = Bh[nb + 4];
                unsigned bl0 = Bl[nb], bl1 = Bl[nb + 4];
                mma_bf16(acc[nt], ah, bh0, bh1);
                mma_bf16(acc[nt], ah, bl0, bl1);
                mma_bf16(acc[nt], al, bh0, bh1);
            }
        }

        int r = (tile << 5) + wm * 16 + g;
        #pragma unroll
        for (int nt = 0; nt < 4; nt++) {
            int c = wn * 32 + nt * 8 + tg * 2;
            if (r < M)
                *(__half2*)&Yh[(size_t)r * 128 + c] =
                    __floats2half2_rn(acc[nt][0], acc[nt][1]);
            if (r + 8 < M)
                *(__half2*)&Yh[(size_t)(r + 8) * 128 + c] =
                    __floats2half2_rn(acc[nt][2], acc[nt][3]);
        }

        __syncthreads();     // all warps done reading Ab
        int nx = tile + 2 * gridDim.x;
        if (nx < ntiles) issue(nx, pp ? a1b : a0b); else cp_commit();
        pp ^= 1;
    }
}

// ---------------- edge conversion (dtype-robust) + dst histogram ----------------
__global__ void convert_edges(const int* __restrict__ raw) {
    bool is64 = true;
    #pragma unroll
    for (int i = 1; i < 128; i += 2)
        if (raw[i] != 0) { is64 = false; break; }
    int e = blockIdx.x * blockDim.x + threadIdx.x;
    if (e >= EE) return;
    int s, d;
    if (is64) { s = raw[2 * e];  d = raw[2 * (EE + e)]; }
    else      { s = raw[e];      d = raw[EE + e]; }
    g_src[e] = s;
    g_dst[e] = d;
    atomicAdd(&g_cnt[d], 1);
}

// ---------------- 3-kernel exclusive scan ----------------
__global__ void scan_part() {
    __shared__ int sm[256];
    int tid = threadIdx.x;
    int i = blockIdx.x * 256 + tid;
    sm[tid] = (i < NN) ? g_cnt[i] : 0;
    __syncthreads();
    for (int o = 128; o; o >>= 1) {
        if (tid < o) sm[tid] += sm[tid + o];
        __syncthreads();
    }
    if (tid == 0) g_part[blockIdx.x] = sm[0];
}

__global__ void scan_tops() {
    __shared__ int sm[256];
    int tid = threadIdx.x;
    int v = (tid < NPART) ? g_part[tid] : 0;
    sm[tid] = v;
    __syncthreads();
    for (int o = 1; o < 256; o <<= 1) {
        int t = sm[tid] + ((tid >= o) ? sm[tid - o] : 0);
        __syncthreads();
        sm[tid] = t;
        __syncthreads();
    }
    if (tid < NPART) g_part[tid] = sm[tid] - v;
}

__global__ void scan_final() {
    __shared__ int sm[256];
    int tid = threadIdx.x;
    int i = blockIdx.x * 256 + tid;
    int v = (i < NN) ? g_cnt[i] : 0;
    sm[tid] = v;
    __syncthreads();
    for (int o = 1; o < 256; o <<= 1) {
        int t = sm[tid] + ((tid >= o) ? sm[tid - o] : 0);
        __syncthreads();
        sm[tid] = t;
        __syncthreads();
    }
    if (i < NN) {
        int excl = sm[tid] - v + g_part[blockIdx.x];
        g_row[i] = excl;
        g_cur[i] = excl;
    }
    if (i == 0) g_row[NN] = EE;
}

// ------- fused edge pass: 2 edges per warp (16-lane halves) --------------------
__global__ void edge_fused(const float* __restrict__ b_p1,
                           const float* __restrict__ W_p2,
                           const float* __restrict__ b_p2) {
    int gw = (blockIdx.x * blockDim.x + threadIdx.x) >> 5;
    int lane = threadIdx.x & 31;
    int half = lane >> 4;
    int hl = lane & 15;
    int e = gw * 2 + half;
    if (e >= EE) return;
    int s = g_src[e];
    int d = g_dst[e];
    float4 a  = row4(g_ABh, s, hl * 4);
    uint2 ub  = *(const uint2*)&g_ABh[(size_t)d * 128 + 64 + hl * 4];
    float2 b01 = __half22float2(*(__half2*)&ub.x);
    float2 b23 = __half22float2(*(__half2*)&ub.y);
    float4 bp = *(const float4*)&b_p1[hl * 4];
    float4 w2 = *(const float4*)&W_p2[hl * 4];
    float h0 = fmaxf(a.x + b01.x + bp.x, 0.f);
    float h1 = fmaxf(a.y + b01.y + bp.y, 0.f);
    float h2 = fmaxf(a.z + b23.x + bp.z, 0.f);
    float h3 = fmaxf(a.w + b23.y + bp.w, 0.f);
    float p = h0 * w2.x + h1 * w2.y + h2 * w2.z + h3 * w2.w;
    #pragma unroll
    for (int o = 8; o; o >>= 1) p += __shfl_xor_sync(0xffffffffu, p, o);
    if (hl == 0) {
        float v = 1.f / (1.f + expf(-(p + b_p2[0])));
        int slot = atomicAdd(&g_cur[d], 1);
        g_csrc[slot] = s;
        g_cw[slot]   = v;
        atomicAdd(&g_deg[d], v);
    }
}

// ---------------- fused dinv + coef: per node ----------------
__global__ void dinv_coef() {
    int n = blockIdx.x * blockDim.x + threadIdx.x;
    if (n >= NN) return;
    float dd = rsqrtf(g_deg[n]);
    g_dinv[n] = dd;
    int e0 = g_row[n], e1 = g_row[n + 1];
    for (int j = e0; j < e1; j++)
        g_cw[j] *= dd * rsqrtf(g_deg[g_csrc[j]]);
}

// ---------------- conv1: warp per node, 4x unroll, relu -> bf16 split ---------
__global__ void conv_relu(const float* __restrict__ bias) {
    int n = blockIdx.x * 8 + (threadIdx.x >> 5);
    int lane = threadIdx.x & 31;
    if (n >= NN) return;
    int f4 = lane * 4;
    float di = g_dinv[n];
    float c0 = di * di;
    float4 b4 = *(const float4*)&bias[f4];
    float4 x0 = row4(g_xlh, n, f4);
    float a0 = b4.x + c0 * x0.x;
    float a1 = b4.y + c0 * x0.y;
    float a2 = b4.z + c0 * x0.z;
    float a3 = b4.w + c0 * x0.w;
    int e0 = g_row[n], e1 = g_row[n + 1];
    int j = e0;
    for (; j + 4 <= e1; j += 4) {
        int s0 = g_csrc[j], s1 = g_csrc[j + 1], s2 = g_csrc[j + 2], s3 = g_csrc[j + 3];
        float w0 = g_cw[j], w1 = g_cw[j + 1], w2 = g_cw[j + 2], w3 = g_cw[j + 3];
        float4 r0 = row4(g_xlh, s0, f4);
        float4 r1 = row4(g_xlh, s1, f4);
        float4 r2 = row4(g_xlh, s2, f4);
        float4 r3 = row4(g_xlh, s3, f4);
        a0 += w0 * r0.x + w1 * r1.x + w2 * r2.x + w3 * r3.x;
        a1 += w0 * r0.y + w1 * r1.y + w2 * r2.y + w3 * r3.y;
        a2 += w0 * r0.z + w1 * r1.z + w2 * r2.z + w3 * r3.z;
        a3 += w0 * r0.w + w1 * r1.w + w2 * r2.w + w3 * r3.w;
    }
    for (; j < e1; j++) {
        int s = g_csrc[j];
        float w = g_cw[j];
        float4 r = row4(g_xlh, s, f4);
        a0 += w * r.x; a1 += w * r.y; a2 += w * r.z; a3 += w * r.w;
    }
    a0 = fmaxf(a0, 0.f); a1 = fmaxf(a1, 0.f);
    a2 = fmaxf(a2, 0.f); a3 = fmaxf(a3, 0.f);
    unsigned h0, l0, h1, l1;
    split2(a0, a1, h0, l0);
    split2(a2, a3, h1, l1);
    uint2* hp = (uint2*)&g_x1hi[(size_t)n * 64 + lane * 2];
    uint2* lp = (uint2*)&g_x1lo[(size_t)n * 64 + lane * 2];
    *hp = make_uint2(h0, h1);
    *lp = make_uint2(l0, l1);
}

// ---------------- conv2 + head: warp per node, shuffle reduction ----------------
__global__ void conv_head(const float* __restrict__ bias,
                          const float* __restrict__ W_lin,
                          const float* __restrict__ b_lin,
                          float* __restrict__ out) {
    int n = blockIdx.x * 8 + (threadIdx.x >> 5);
    int lane = threadIdx.x & 31;
    if (n >= NN) return;
    int f4 = lane * 4;
    float di = g_dinv[n];
    float c0 = di * di;
    float4 b4 = *(const float4*)&bias[f4];
    float4 x0 = row4(g_xlh, n, f4);
    float a0 = b4.x + c0 * x0.x;
    float a1 = b4.y + c0 * x0.y;
    float a2 = b4.z + c0 * x0.z;
    float a3 = b4.w + c0 * x0.w;
    int e0 = g_row[n], e1 = g_row[n + 1];
    int j = e0;
    for (; j + 4 <= e1; j += 4) {
        int s0 = g_csrc[j], s1 = g_csrc[j + 1], s2 = g_csrc[j + 2], s3 = g_csrc[j + 3];
        float w0 = g_cw[j], w1 = g_cw[j + 1], w2 = g_cw[j + 2], w3 = g_cw[j + 3];
        float4 r0 = row4(g_xlh, s0, f4);
        float4 r1 = row4(g_xlh, s1, f4);
        float4 r2 = row4(g_xlh, s2, f4);
        float4 r3 = row4(g_xlh, s3, f4);
        a0 += w0 * r0.x + w1 * r1.x + w2 * r2.x + w3 * r3.x;
        a1 += w0 * r0.y + w1 * r1.y + w2 * r2.y + w3 * r3.y;
        a2 += w0 * r0.z + w1 * r1.z + w2 * r2.z + w3 * r3.z;
        a3 += w0 * r0.w + w1 * r1.w + w2 * r2.w + w3 * r3.w;
    }
    for (; j < e1; j++) {
        int s = g_csrc[j];
        float w = g_cw[j];
        float4 r = row4(g_xlh, s, f4);
        a0 += w * r.x; a1 += w * r.y; a2 += w * r.z; a3 += w * r.w;
    }
    float v0 = fmaxf(a0, 0.f), v1 = fmaxf(a1, 0.f);
    float v2 = fmaxf(a2, 0.f), v3 = fmaxf(a3, 0.f);
    float4 wl0 = *(const float4*)&W_lin[f4];
    float4 wl1 = *(const float4*)&W_lin[128 + f4];
    float p0 = v0 * wl0.x + v1 * wl0.y + v2 * wl0.z + v3 * wl0.w;
    float p1 = v0 * wl1.x + v1 * wl1.y + v2 * wl1.z + v3 * wl1.w;
    #pragma unroll
    for (int o = 16; o; o >>= 1) {
        p0 += __shfl_xor_sync(0xffffffffu, p0, o);
        p1 += __shfl_xor_sync(0xffffffffu, p1, o);
    }
    if (lane == 0) {
        out[2 * n + 0] = 1.f / (1.f + expf(-(p0 + b_lin[0])));
        out[2 * n + 1] = 1.f / (1.f + expf(-(p1 + b_lin[1])));
    }
}

// ---------------- host ----------------
extern "C" void kernel_launch(void* const* d_in, const int* in_sizes, int n_in,
                              void* d_out, int out_size) {
    const float* x     = (const float*)d_in[0];
    const int*   ei    = (const int*)d_in[1];
    const float* W_p1  = (const float*)d_in[2];
    const float* b_p1  = (const float*)d_in[3];
    const float* W_p2  = (const float*)d_in[4];
    const float* b_p2  = (const float*)d_in[5];
    const float* W1    = (const float*)d_in[6];
    const float* b1    = (const float*)d_in[7];
    const float* W2    = (const float*)d_in[8];
    const float* b2    = (const float*)d_in[9];
    const float* W_lin = (const float*)d_in[10];
    const float* b_lin = (const float*)d_in[11];
    float* out = (float*)d_out;

    void *pABh, *pXLh, *pXhi, *pXlo, *pX1hi, *pX1lo, *pBhi, *pBlo;
    cudaGetSymbolAddress(&pABh,  g_ABh);
    cudaGetSymbolAddress(&pXLh,  g_xlh);
    cudaGetSymbolAddress(&pXhi,  g_xhi);
    cudaGetSymbolAddress(&pXlo,  g_xlo);
    cudaGetSymbolAddress(&pX1hi, g_x1hi);
    cudaGetSymbolAddress(&pX1lo, g_x1lo);
    cudaGetSymbolAddress(&pBhi,  g_Bhi);
    cudaGetSymbolAddress(&pBlo,  g_Blo);
    const unsigned* Bhi = (const unsigned*)pBhi;
    const unsigned* Blo = (const unsigned*)pBlo;
    const unsigned* Xhi = (const unsigned*)pXhi;
    const unsigned* Xlo = (const unsigned*)pXlo;

    const int MMA_SMEM = 26112 * 4;  // 104448 B -> 2 CTAs/SM
    cudaFuncSetAttribute(gemm_mma, cudaFuncAttributeMaxDynamicSharedMemorySize, MMA_SMEM);

    const int GRID        = 296;
    const int edge_blocks = (EE / 2 + 7) / 8;
    const int e_blocks    = (EE + 255) / 256;
    const int n_blocks    = (NN + 255) / 256;
    const int conv_blocks = (NN + 7) / 8;
    const int xsplit_blocks = (NN * 64 + 255) / 256;   // 12500

    init_misc<<<NPART + 96 + xsplit_blocks, 256>>>(x, W_p1, W1, W2);      // 0
    convert_edges<<<e_blocks, 256>>>(ei);                                 // 1
    scan_part<<<NPART, 256>>>();                                          // 2
    gemm_mma<<<GRID, 256, MMA_SMEM>>>(Xhi, Xlo, Bhi, Blo,
                                      (__half*)pABh, NN);                 // 3 (profiled)
    scan_tops<<<1, 256>>>();                                              // 4
    scan_final<<<NPART, 256>>>();                                         // 5
    edge_fused<<<edge_blocks, 256>>>(b_p1, W_p2, b_p2);                   // 6
    dinv_coef<<<n_blocks, 256>>>();                                       // 7
    gemm_mma<<<GRID, 256, MMA_SMEM>>>(Xhi, Xlo, Bhi + 8192, Blo + 8192,
                                      (__half*)pXLh, NN);                 // 8
    conv_relu<<<conv_blocks, 256>>>(b1);                                  // 9
    gemm_mma<<<GRID, 256, MMA_SMEM>>>((const unsigned*)pX1hi,
                                      (const unsigned*)pX1lo,
                                      Bhi + 16384, Blo + 16384,
                                      (__half*)pXLh, NN);                 // 10
    conv_head<<<conv_blocks, 256>>>(b2, W_lin, b_lin, out);               // 11
}

// round 15
// speedup vs baseline: 1.0777x; 1.0777x over previous
#include <cuda_runtime.h>
#include <cuda_bf16.h>
#include <cuda_fp16.h>
#include <cstdint>

#define NN 50000
#define EE 600000
#define NPART 196   // ceil(NN/256)

// ---------------- device scratch ----------------
__device__ __align__(16) float  g_deg[NN];
__device__ __align__(16) float  g_dinv[NN];
__device__ __align__(16) __half g_ABh[NN * 128];   // edge-MLP table (fp16)
__device__ __align__(16) __half g_xlh[NN * 128];   // conv message table (fp16)
__device__ __align__(16) float  g_x1[NN * 128];    // conv1 output (fp32)
__device__ __align__(16) int    g_src[EE];
__device__ __align__(16) int    g_dst[EE];
__device__ __align__(16) int    g_cnt[NN];
__device__ __align__(16) int    g_part[256];
__device__ __align__(16) int    g_row[NN + 1];
__device__ __align__(16) int    g_cur[NN];
__device__ __align__(16) int    g_csrc[EE];
__device__ __align__(16) float  g_cw[EE];
// bf16 hi/lo weights, row-major packed bf16x2: [mat][n*64 + colpair]
__device__ __align__(16) unsigned g_Bhi[3][8192];
__device__ __align__(16) unsigned g_Blo[3][8192];

// ---------------- PTX helpers (base PTX only) ----------------
__device__ __forceinline__ void mma_bf16(float* c, const unsigned* a,
                                         unsigned b0, unsigned b1) {
    asm volatile(
        "mma.sync.aligned.m16n8k16.row.col.f32.bf16.bf16.f32 "
        "{%0,%1,%2,%3}, {%4,%5,%6,%7}, {%8,%9}, {%0,%1,%2,%3};"
        : "+f"(c[0]), "+f"(c[1]), "+f"(c[2]), "+f"(c[3])
        : "r"(a[0]), "r"(a[1]), "r"(a[2]), "r"(a[3]), "r"(b0), "r"(b1));
}
__device__ __forceinline__ uint32_t smem_u32(const void* p) {
    uint32_t a;
    asm("{ .reg .u64 t; cvta.to.shared.u64 t, %1; cvt.u32.u64 %0, t; }"
        : "=r"(a) : "l"(p));
    return a;
}
__device__ __forceinline__ void cp_async16(uint32_t dst, const void* src, int nbytes) {
    asm volatile("cp.async.cg.shared.global [%0], [%1], 16, %2;"
                 :: "r"(dst), "l"(src), "r"(nbytes) : "memory");
}
__device__ __forceinline__ void cp_commit() {
    asm volatile("cp.async.commit_group;" ::: "memory");
}
__device__ __forceinline__ void cp_wait0() {
    asm volatile("cp.async.wait_group 0;" ::: "memory");
}
__device__ __forceinline__ void cp_wait1() {
    asm volatile("cp.async.wait_group 1;" ::: "memory");
}
// gather 4 features from a fp16 table row
__device__ __forceinline__ float4 row4(const __half* tab, int s, int f4) {
    uint2 u = *(const uint2*)&tab[(size_t)s * 128 + f4];
    float2 f01 = __half22float2(*(__half2*)&u.x);
    float2 f23 = __half22float2(*(__half2*)&u.y);
    return make_float4(f01.x, f01.y, f23.x, f23.y);
}
__device__ __forceinline__ void split2(float f0, float f1, unsigned& uh, unsigned& ul) {
    __nv_bfloat162 h = __floats2bfloat162_rn(f0, f1);
    __nv_bfloat162 l = __floats2bfloat162_rn(f0 - __bfloat162float(h.x),
                                             f1 - __bfloat162float(h.y));
    uh = *(unsigned*)&h;
    ul = *(unsigned*)&l;
}

// ---------------- init: zero cnt, deg=1, split-bf16 weights ----------------
__global__ void init_misc(const float* __restrict__ Wp1,
                          const float* __restrict__ W1,
                          const float* __restrict__ W2) {
    if (blockIdx.x < NPART) {
        int i = blockIdx.x * 256 + threadIdx.x;
        if (i < NN) { g_cnt[i] = 0; g_deg[i] = 1.0f; }
        return;
    }
    int idx = (blockIdx.x - NPART) * 256 + threadIdx.x;   // 3*8192 pairs
    if (idx >= 3 * 8192) return;
    int m  = idx >> 13;
    int p  = idx & 8191;
    int n  = p >> 6;
    int k  = (p & 63) * 2;
    float f0, f1;
    if (m == 0) {
        f0 = (n < 64) ? Wp1[n * 256 + k]     : Wp1[(n - 64) * 256 + 128 + k];
        f1 = (n < 64) ? Wp1[n * 256 + k + 1] : Wp1[(n - 64) * 256 + 128 + k + 1];
    } else if (m == 1) { f0 = W1[n * 128 + k]; f1 = W1[n * 128 + k + 1]; }
    else               { f0 = W2[n * 128 + k]; f1 = W2[n * 128 + k + 1]; }
    split2(f0, f1, g_Bhi[m][p], g_Blo[m][p]);
}

#define RS 68

// ---------------- fused GEMM1+2: both tables from one x pass ----------------
// ABh = fp16(x @ Bp^T), xlh = fp16(x @ B1^T). 32-row tiles, 2-deep pipeline.
// smem words: St0 4096 | St1 4096 | Ah 2176 | Al 2176 | Bh 17408 | Bl 17408
__global__ void __launch_bounds__(256, 1)
gemm12(const float* __restrict__ X,
       const unsigned* __restrict__ Bhi, const unsigned* __restrict__ Blo,
       __half* __restrict__ Y0, __half* __restrict__ Y1, int M) {
    extern __shared__ unsigned sm[];
    float*    St0 = (float*)sm;
    float*    St1 = (float*)(sm + 4096);
    unsigned* Ah  = sm + 8192;
    unsigned* Al  = sm + 10368;
    unsigned* Bh  = sm + 12544;
    unsigned* Bl  = sm + 29952;
    const uint32_t st0b = smem_u32(St0);
    const uint32_t st1b = smem_u32(St1);

    const int tid  = threadIdx.x;
    const int lane = tid & 31;
    const int warp = tid >> 5;
    const int wm = warp & 1;
    const int wn = warp >> 1;
    const int g  = lane >> 2;
    const int tg = lane & 3;

    const int ntiles = (M + 31) >> 5;

    auto issue = [&](int tile, uint32_t stb) {
        int row0 = tile << 5;
        #pragma unroll
        for (int k = 0; k < 4; k++) {
            int idx = tid + k * 256;          // 1024 16B chunks
            int r = idx >> 5, c4 = idx & 31;
            int gr = row0 + r;
            cp_async16(stb + idx * 16,
                       X + (size_t)gr * 128 + c4 * 4, (gr < M) ? 16 : 0);
        }
        cp_commit();
    };

    int t0 = blockIdx.x;
    int t1 = t0 + gridDim.x;
    if (t0 < ntiles) issue(t0, st0b); else cp_commit();
    if (t1 < ntiles) issue(t1, st1b); else cp_commit();

    // stage both weight mats (hi+lo): 16384 pairs
    #pragma unroll 4
    for (int i = tid; i < 16384; i += 256) {
        int m = i >> 13;
        int p = i & 8191;
        int n = p >> 6, cp = p & 63;
        Bh[m * 8704 + n * RS + cp] = Bhi[i];
        Bl[m * 8704 + n * RS + cp] = Blo[i];
    }

    int pp = 0;
    for (int tile = t0; tile < ntiles; tile += gridDim.x) {
        cp_wait1();
        __syncthreads();     // stage full; prev iter's Ah/Al reads done
        float* St = pp ? St1 : St0;

        // convert stage -> Ah/Al
        #pragma unroll
        for (int k = 0; k < 8; k++) {
            int idx = tid + k * 256;
            int r = idx >> 6, cp = idx & 63;
            float2 f = *(const float2*)&St[idx * 2];
            split2(f.x, f.y, Ah[r * RS + cp], Al[r * RS + cp]);
        }
        __syncthreads();     // Ah/Al ready; stage reads done

        int nx = tile + 2 * gridDim.x;
        if (nx < ntiles) issue(nx, pp ? st1b : st0b); else cp_commit();

        // fragments once, two weight mats
        unsigned ahf[8][4], alf[8][4];
        #pragma unroll
        for (int kc = 0; kc < 8; kc++) {
            int w0 = (wm * 16 + g) * RS + kc * 8 + tg;
            ahf[kc][0] = Ah[w0];
            ahf[kc][1] = Ah[w0 + 8 * RS];
            ahf[kc][2] = Ah[w0 + 4];
            ahf[kc][3] = Ah[w0 + 8 * RS + 4];
            alf[kc][0] = Al[w0];
            alf[kc][1] = Al[w0 + 8 * RS];
            alf[kc][2] = Al[w0 + 4];
            alf[kc][3] = Al[w0 + 8 * RS + 4];
        }

        int r = (tile << 5) + wm * 16 + g;
        #pragma unroll
        for (int m = 0; m < 2; m++) {
            float acc[4][4];
            #pragma unroll
            for (int nt = 0; nt < 4; nt++)
                #pragma unroll
                for (int q = 0; q < 4; q++) acc[nt][q] = 0.f;
            #pragma unroll
            for (int kc = 0; kc < 8; kc++) {
                #pragma unroll
                for (int nt = 0; nt < 4; nt++) {
                    int nb = m * 8704 + (wn * 32 + nt * 8 + g) * RS + kc * 8 + tg;
                    unsigned bh0 = Bh[nb], bh1 = Bh[nb + 4];
                    unsigned bl0 = Bl[nb], bl1 = Bl[nb + 4];
                    mma_bf16(acc[nt], ahf[kc], bh0, bh1);
                    mma_bf16(acc[nt], ahf[kc], bl0, bl1);
                    mma_bf16(acc[nt], alf[kc], bh0, bh1);
                }
            }
            __half* Yh = m ? Y1 : Y0;
            #pragma unroll
            for (int nt = 0; nt < 4; nt++) {
                int c = wn * 32 + nt * 8 + tg * 2;
                if (r < M)
                    *(__half2*)&Yh[(size_t)r * 128 + c] =
                        __floats2half2_rn(acc[nt][0], acc[nt][1]);
                if (r + 8 < M)
                    *(__half2*)&Yh[(size_t)(r + 8) * 128 + c] =
                        __floats2half2_rn(acc[nt][2], acc[nt][3]);
            }
        }
        pp ^= 1;
    }
}

// ---------------- GEMM3 (R13 style): fp32 in, in-kernel convert ----------------
__global__ void __launch_bounds__(256, 2)
gemm_mma(const float* __restrict__ X, const unsigned* __restrict__ Bhi,
         const unsigned* __restrict__ Blo, __half* __restrict__ Yh, int M) {
    extern __shared__ unsigned sm[];
    float*    St = (float*)sm;                 // 4096 words
    unsigned* Ah = sm + 4096;
    unsigned* Al = sm + 4096 + 32 * RS;
    unsigned* Bh = sm + 4096 + 64 * RS;
    unsigned* Bl = sm + 4096 + 64 * RS + 128 * RS;
    const uint32_t st_base = smem_u32(St);

    const int tid  = threadIdx.x;
    const int lane = tid & 31;
    const int warp = tid >> 5;
    const int wm = warp & 1;
    const int wn = warp >> 1;
    const int g  = lane >> 2;
    const int tg = lane & 3;

    const int ntiles = (M + 31) >> 5;
    int tile = blockIdx.x;

    if (tile < ntiles) {
        #pragma unroll
        for (int k = 0; k < 4; k++) {
            int idx = tid + k * 256;
            int r = idx >> 5, c4 = idx & 31;
            int gr = (tile << 5) + r;
            cp_async16(st_base + idx * 16,
                       X + (size_t)gr * 128 + c4 * 4, (gr < M) ? 16 : 0);
        }
    }
    cp_commit();

    #pragma unroll 4
    for (int i = tid; i < 8192; i += 256) {
        int n = i >> 6, cp = i & 63;
        Bh[n * RS + cp] = Bhi[i];
        Bl[n * RS + cp] = Blo[i];
    }

    for (; tile < ntiles; tile += gridDim.x) {
        const int row0 = tile << 5;
        cp_wait0();
        __syncthreads();

        #pragma unroll
        for (int k = 0; k < 8; k++) {
            int idx = tid + k * 256;
            int r = idx >> 6, cp = idx & 63;
            float2 f = *(const float2*)&St[idx * 2];
            split2(f.x, f.y, Ah[r * RS + cp], Al[r * RS + cp]);
        }
        __syncthreads();

        int nxt = tile + gridDim.x;
        if (nxt < ntiles) {
            #pragma unroll
            for (int k = 0; k < 4; k++) {
                int idx = tid + k * 256;
                int r = idx >> 5, c4 = idx & 31;
                int gr = (nxt << 5) + r;
                cp_async16(st_base + idx * 16,
                           X + (size_t)gr * 128 + c4 * 4, (gr < M) ? 16 : 0);
            }
        }
        cp_commit();

        float acc[4][4];
        #pragma unroll
        for (int nt = 0; nt < 4; nt++)
            #pragma unroll
            for (int q = 0; q < 4; q++) acc[nt][q] = 0.f;

        #pragma unroll
        for (int kc = 0; kc < 8; kc++) {
            unsigned ah[4], al[4];
            int w0 = (wm * 16 + g) * RS + kc * 8 + tg;
            ah[0] = Ah[w0];
            ah[1] = Ah[w0 + 8 * RS];
            ah[2] = Ah[w0 + 4];
            ah[3] = Ah[w0 + 8 * RS + 4];
            al[0] = Al[w0];
            al[1] = Al[w0 + 8 * RS];
            al[2] = Al[w0 + 4];
            al[3] = Al[w0 + 8 * RS + 4];
            #pragma unroll
            for (int nt = 0; nt < 4; nt++) {
                int nb = (wn * 32 + nt * 8 + g) * RS + kc * 8 + tg;
                unsigned bh0 = Bh[nb], bh1 = Bh[nb + 4];
                unsigned bl0 = Bl[nb], bl1 = Bl[nb + 4];
                mma_bf16(acc[nt], ah, bh0, bh1);
                mma_bf16(acc[nt], ah, bl0, bl1);
                mma_bf16(acc[nt], al, bh0, bh1);
            }
        }

        int r = row0 + wm * 16 + g;
        #pragma unroll
        for (int nt = 0; nt < 4; nt++) {
            int c = wn * 32 + nt * 8 + tg * 2;
            if (r < M)
                *(__half2*)&Yh[(size_t)r * 128 + c] =
                    __floats2half2_rn(acc[nt][0], acc[nt][1]);
            if (r + 8 < M)
                *(__half2*)&Yh[(size_t)(r + 8) * 128 + c] =
                    __floats2half2_rn(acc[nt][2], acc[nt][3]);
        }
    }
}

// ---------------- edge conversion (dtype-robust) + dst histogram ----------------
__global__ void convert_edges(const int* __restrict__ raw) {
    bool is64 = true;
    #pragma unroll
    for (int i = 1; i < 128; i += 2)
        if (raw[i] != 0) { is64 = false; break; }
    int e = blockIdx.x * blockDim.x + threadIdx.x;
    if (e >= EE) return;
    int s, d;
    if (is64) { s = raw[2 * e];  d = raw[2 * (EE + e)]; }
    else      { s = raw[e];      d = raw[EE + e]; }
    g_src[e] = s;
    g_dst[e] = d;
    atomicAdd(&g_cnt[d], 1);
}

// ---------------- 3-kernel exclusive scan ----------------
__global__ void scan_part() {
    __shared__ int sm[256];
    int tid = threadIdx.x;
    int i = blockIdx.x * 256 + tid;
    sm[tid] = (i < NN) ? g_cnt[i] : 0;
    __syncthreads();
    for (int o = 128; o; o >>= 1) {
        if (tid < o) sm[tid] += sm[tid + o];
        __syncthreads();
    }
    if (tid == 0) g_part[blockIdx.x] = sm[0];
}

__global__ void scan_tops() {
    __shared__ int sm[256];
    int tid = threadIdx.x;
    int v = (tid < NPART) ? g_part[tid] : 0;
    sm[tid] = v;
    __syncthreads();
    for (int o = 1; o < 256; o <<= 1) {
        int t = sm[tid] + ((tid >= o) ? sm[tid - o] : 0);
        __syncthreads();
        sm[tid] = t;
        __syncthreads();
    }
    if (tid < NPART) g_part[tid] = sm[tid] - v;
}

__global__ void scan_final() {
    __shared__ int sm[256];
    int tid = threadIdx.x;
    int i = blockIdx.x * 256 + tid;
    int v = (i < NN) ? g_cnt[i] : 0;
    sm[tid] = v;
    __syncthreads();
    for (int o = 1; o < 256; o <<= 1) {
        int t = sm[tid] + ((tid >= o) ? sm[tid - o] : 0);
        __syncthreads();
        sm[tid] = t;
        __syncthreads();
    }
    if (i < NN) {
        int excl = sm[tid] - v + g_part[blockIdx.x];
        g_row[i] = excl;
        g_cur[i] = excl;
    }
    if (i == 0) g_row[NN] = EE;
}

// ------- fused edge pass: 2 edges per warp (16-lane halves) --------------------
__global__ void edge_fused(const float* __restrict__ b_p1,
                           const float* __restrict__ W_p2,
                           const float* __restrict__ b_p2) {
    int gw = (blockIdx.x * blockDim.x + threadIdx.x) >> 5;
    int lane = threadIdx.x & 31;
    int half = lane >> 4;
    int hl = lane & 15;
    int e = gw * 2 + half;
    if (e >= EE) return;
    int s = g_src[e];
    int d = g_dst[e];
    float4 a  = row4(g_ABh, s, hl * 4);
    uint2 ub  = *(const uint2*)&g_ABh[(size_t)d * 128 + 64 + hl * 4];
    float2 b01 = __half22float2(*(__half2*)&ub.x);
    float2 b23 = __half22float2(*(__half2*)&ub.y);
    float4 bp = *(const float4*)&b_p1[hl * 4];
    float4 w2 = *(const float4*)&W_p2[hl * 4];
    float h0 = fmaxf(a.x + b01.x + bp.x, 0.f);
    float h1 = fmaxf(a.y + b01.y + bp.y, 0.f);
    float h2 = fmaxf(a.z + b23.x + bp.z, 0.f);
    float h3 = fmaxf(a.w + b23.y + bp.w, 0.f);
    float p = h0 * w2.x + h1 * w2.y + h2 * w2.z + h3 * w2.w;
    #pragma unroll
    for (int o = 8; o; o >>= 1) p += __shfl_xor_sync(0xffffffffu, p, o);
    if (hl == 0) {
        float v = 1.f / (1.f + expf(-(p + b_p2[0])));
        int slot = atomicAdd(&g_cur[d], 1);
        g_csrc[slot] = s;
        g_cw[slot]   = v;
        atomicAdd(&g_deg[d], v);
    }
}

// ---------------- fused dinv + coef ----------------
__global__ void dinv_coef() {
    int n = blockIdx.x * blockDim.x + threadIdx.x;
    if (n >= NN) return;
    float dd = rsqrtf(g_deg[n]);
    g_dinv[n] = dd;
    int e0 = g_row[n], e1 = g_row[n + 1];
    for (int j = e0; j < e1; j++)
        g_cw[j] *= dd * rsqrtf(g_deg[g_csrc[j]]);
}

// ---------------- conv1: warp per node, 4x unroll, relu -> fp32 ----------------
__global__ void conv_relu(const float* __restrict__ bias) {
    int n = blockIdx.x * 8 + (threadIdx.x >> 5);
    int lane = threadIdx.x & 31;
    if (n >= NN) return;
    int f4 = lane * 4;
    float di = g_dinv[n];
    float c0 = di * di;
    float4 b4 = *(const float4*)&bias[f4];
    float4 x0 = row4(g_xlh, n, f4);
    float a0 = b4.x + c0 * x0.x;
    float a1 = b4.y + c0 * x0.y;
    float a2 = b4.z + c0 * x0.z;
    float a3 = b4.w + c0 * x0.w;
    int e0 = g_row[n], e1 = g_row[n + 1];
    int j = e0;
    for (; j + 4 <= e1; j += 4) {
        int s0 = g_csrc[j], s1 = g_csrc[j + 1], s2 = g_csrc[j + 2], s3 = g_csrc[j + 3];
        float w0 = g_cw[j], w1 = g_cw[j + 1], w2 = g_cw[j + 2], w3 = g_cw[j + 3];
        float4 r0 = row4(g_xlh, s0, f4);
        float4 r1 = row4(g_xlh, s1, f4);
        float4 r2 = row4(g_xlh, s2, f4);
        float4 r3 = row4(g_xlh, s3, f4);
        a0 += w0 * r0.x + w1 * r1.x + w2 * r2.x + w3 * r3.x;
        a1 += w0 * r0.y + w1 * r1.y + w2 * r2.y + w3 * r3.y;
        a2 += w0 * r0.z + w1 * r1.z + w2 * r2.z + w3 * r3.z;
        a3 += w0 * r0.w + w1 * r1.w + w2 * r2.w + w3 * r3.w;
    }
    for (; j < e1; j++) {
        int s = g_csrc[j];
        float w = g_cw[j];
        float4 r = row4(g_xlh, s, f4);
        a0 += w * r.x; a1 += w * r.y; a2 += w * r.z; a3 += w * r.w;
    }
    *(float4*)&g_x1[(size_t)n * 128 + f4] =
        make_float4(fmaxf(a0, 0.f), fmaxf(a1, 0.f), fmaxf(a2, 0.f), fmaxf(a3, 0.f));
}

// ---------------- conv2 + head: warp per node, shuffle reduction ----------------
__global__ void conv_head(const float* __restrict__ bias,
                          const float* __restrict__ W_lin,
                          const float* __restrict__ b_lin,
                          float* __restrict__ out) {
    int n = blockIdx.x * 8 + (threadIdx.x >> 5);
    int lane = threadIdx.x & 31;
    if (n >= NN) return;
    int f4 = lane * 4;
    float di = g_dinv[n];
    float c0 = di * di;
    float4 b4 = *(const float4*)&bias[f4];
    float4 x0 = row4(g_xlh, n, f4);
    float a0 = b4.x + c0 * x0.x;
    float a1 = b4.y + c0 * x0.y;
    float a2 = b4.z + c0 * x0.z;
    float a3 = b4.w + c0 * x0.w;
    int e0 = g_row[n], e1 = g_row[n + 1];
    int j = e0;
    for (; j + 4 <= e1; j += 4) {
        int s0 = g_csrc[j], s1 = g_csrc[j + 1], s2 = g_csrc[j + 2], s3 = g_csrc[j + 3];
        float w0 = g_cw[j], w1 = g_cw[j + 1], w2 = g_cw[j + 2], w3 = g_cw[j + 3];
        float4 r0 = row4(g_xlh, s0, f4);
        float4 r1 = row4(g_xlh, s1, f4);
        float4 r2 = row4(g_xlh, s2, f4);
        float4 r3 = row4(g_xlh, s3, f4);
        a0 += w0 * r0.x + w1 * r1.x + w2 * r2.x + w3 * r3.x;
        a1 += w0 * r0.y + w1 * r1.y + w2 * r2.y + w3 * r3.y;
        a2 += w0 * r0.z + w1 * r1.z + w2 * r2.z + w3 * r3.z;
        a3 += w0 * r0.w + w1 * r1.w + w2 * r2.w + w3 * r3.w;
    }
    for (; j < e1; j++) {
        int s = g_csrc[j];
        float w = g_cw[j];
        float4 r = row4(g_xlh, s, f4);
        a0 += w * r.x; a1 += w * r.y; a2 += w * r.z; a3 += w * r.w;
    }
    float v0 = fmaxf(a0, 0.f), v1 = fmaxf(a1, 0.f);
    float v2 = fmaxf(a2, 0.f), v3 = fmaxf(a3, 0.f);
    float4 wl0 = *(const float4*)&W_lin[f4];
    float4 wl1 = *(const float4*)&W_lin[128 + f4];
    float p0 = v0 * wl0.x + v1 * wl0.y + v2 * wl0.z + v3 * wl0.w;
    float p1 = v0 * wl1.x + v1 * wl1.y + v2 * wl1.z + v3 * wl1.w;
    #pragma unroll
    for (int o = 16; o; o >>= 1) {
        p0 += __shfl_xor_sync(0xffffffffu, p0, o);
        p1 += __shfl_xor_sync(0xffffffffu, p1, o);
    }
    if (lane == 0) {
        out[2 * n + 0] = 1.f / (1.f + expf(-(p0 + b_lin[0])));
        out[2 * n + 1] = 1.f / (1.f + expf(-(p1 + b_lin[1])));
    }
}

// ---------------- host ----------------
extern "C" void kernel_launch(void* const* d_in, const int* in_sizes, int n_in,
                              void* d_out, int out_size) {
    const float* x     = (const float*)d_in[0];
    const int*   ei    = (const int*)d_in[1];
    const float* W_p1  = (const float*)d_in[2];
    const float* b_p1  = (const float*)d_in[3];
    const float* W_p2  = (const float*)d_in[4];
    const float* b_p2  = (const float*)d_in[5];
    const float* W1    = (const float*)d_in[6];
    const float* b1    = (const float*)d_in[7];
    const float* W2    = (const float*)d_in[8];
    const float* b2    = (const float*)d_in[9];
    const float* W_lin = (const float*)d_in[10];
    const float* b_lin = (const float*)d_in[11];
    float* out = (float*)d_out;

    void *pABh, *pXLh, *pX1, *pBhi, *pBlo;
    cudaGetSymbolAddress(&pABh, g_ABh);
    cudaGetSymbolAddress(&pXLh, g_xlh);
    cudaGetSymbolAddress(&pX1,  g_x1);
    cudaGetSymbolAddress(&pBhi, g_Bhi);
    cudaGetSymbolAddress(&pBlo, g_Blo);
    const unsigned* Bhi = (const unsigned*)pBhi;
    const unsigned* Blo = (const unsigned*)pBlo;

    const int G12_SMEM = 47360 * 4;   // 189440 B -> 1 CTA/SM
    const int G3_SMEM  = 26112 * 4;   // 104448 B -> 2 CTAs/SM
    cudaFuncSetAttribute(gemm12,   cudaFuncAttributeMaxDynamicSharedMemorySize, G12_SMEM);
    cudaFuncSetAttribute(gemm_mma, cudaFuncAttributeMaxDynamicSharedMemorySize, G3_SMEM);

    const int edge_blocks = (EE / 2 + 7) / 8;
    const int e_blocks    = (EE + 255) / 256;
    const int n_blocks    = (NN + 255) / 256;
    const int conv_blocks = (NN + 7) / 8;

    init_misc<<<NPART + 96, 256>>>(W_p1, W1, W2);                         // 0
    convert_edges<<<e_blocks, 256>>>(ei);                                 // 1
    scan_part<<<NPART, 256>>>();                                          // 2
    gemm12<<<148, 256, G12_SMEM>>>(x, Bhi, Blo, (__half*)pABh,
                                   (__half*)pXLh, NN);                    // 3 (profiled)
    scan_tops<<<1, 256>>>();                                              // 4
    scan_final<<<NPART, 256>>>();                                         // 5
    edge_fused<<<edge_blocks, 256>>>(b_p1, W_p2, b_p2);                   // 6
    dinv_coef<<<n_blocks, 256>>>();                                       // 7
    conv_relu<<<conv_blocks, 256>>>(b1);                                  // 8
    gemm_mma<<<296, 256, G3_SMEM>>>((const float*)pX1, Bhi + 16384,
                                    Blo + 16384, (__half*)pXLh, NN);      // 9
    conv_head<<<conv_blocks, 256>>>(b2, W_lin, b_lin, out);               // 10
}

// round 16
// speedup vs baseline: 1.0802x; 1.0023x over previous
#include <cuda_runtime.h>
#include <cuda_bf16.h>
#include <cuda_fp16.h>
#include <cstdint>

#define NN 50000
#define EE 600000
#define NPART 196   // ceil(NN/256)

// ---------------- device scratch ----------------
__device__ __align__(16) float  g_deg[NN];
__device__ __align__(16) float  g_dinv[NN];
__device__ __align__(16) __half g_ABh[NN * 128];   // edge-MLP table (fp16)
__device__ __align__(16) __half g_xlh[NN * 128];   // conv message table (fp16)
__device__ __align__(16) float  g_x1[NN * 128];    // conv1 output (fp32)
__device__ __align__(16) int    g_src[EE];
__device__ __align__(16) int    g_dst[EE];
__device__ __align__(16) int    g_cnt[NN];
__device__ __align__(16) int    g_part[256];
__device__ __align__(16) int    g_row[NN + 1];
__device__ __align__(16) int    g_cur[NN];
__device__ __align__(16) int    g_csrc[EE];
__device__ __align__(16) float  g_cw[EE];
// bf16 hi/lo weights, row-major packed bf16x2: [mat][n*64 + colpair]
__device__ __align__(16) unsigned g_Bhi[3][8192];
__device__ __align__(16) unsigned g_Blo[3][8192];

// ---------------- PTX helpers (base PTX only) ----------------
__device__ __forceinline__ void mma_bf16(float* c, const unsigned* a,
                                         unsigned b0, unsigned b1) {
    asm volatile(
        "mma.sync.aligned.m16n8k16.row.col.f32.bf16.bf16.f32 "
        "{%0,%1,%2,%3}, {%4,%5,%6,%7}, {%8,%9}, {%0,%1,%2,%3};"
        : "+f"(c[0]), "+f"(c[1]), "+f"(c[2]), "+f"(c[3])
        : "r"(a[0]), "r"(a[1]), "r"(a[2]), "r"(a[3]), "r"(b0), "r"(b1));
}
__device__ __forceinline__ uint32_t smem_u32(const void* p) {
    uint32_t a;
    asm("{ .reg .u64 t; cvta.to.shared.u64 t, %1; cvt.u32.u64 %0, t; }"
        : "=r"(a) : "l"(p));
    return a;
}
__device__ __forceinline__ void cp_async16(uint32_t dst, const void* src, int nbytes) {
    asm volatile("cp.async.cg.shared.global [%0], [%1], 16, %2;"
                 :: "r"(dst), "l"(src), "r"(nbytes) : "memory");
}
__device__ __forceinline__ void cp_commit() {
    asm volatile("cp.async.commit_group;" ::: "memory");
}
__device__ __forceinline__ void cp_wait0() {
    asm volatile("cp.async.wait_group 0;" ::: "memory");
}
__device__ __forceinline__ void cp_wait1() {
    asm volatile("cp.async.wait_group 1;" ::: "memory");
}
// gather 4 features from a fp16 table row
__device__ __forceinline__ float4 row4(const __half* tab, int s, int f4) {
    uint2 u = *(const uint2*)&tab[(size_t)s * 128 + f4];
    float2 f01 = __half22float2(*(__half2*)&u.x);
    float2 f23 = __half22float2(*(__half2*)&u.y);
    return make_float4(f01.x, f01.y, f23.x, f23.y);
}
__device__ __forceinline__ void split2(float f0, float f1, unsigned& uh, unsigned& ul) {
    __nv_bfloat162 h = __floats2bfloat162_rn(f0, f1);
    __nv_bfloat162 l = __floats2bfloat162_rn(f0 - __bfloat162float(h.x),
                                             f1 - __bfloat162float(h.y));
    uh = *(unsigned*)&h;
    ul = *(unsigned*)&l;
}

// ---------------- init: zero cnt, deg=1, split-bf16 weights ----------------
__global__ void init_misc(const float* __restrict__ Wp1,
                          const float* __restrict__ W1,
                          const float* __restrict__ W2) {
    if (blockIdx.x < NPART) {
        int i = blockIdx.x * 256 + threadIdx.x;
        if (i < NN) { g_cnt[i] = 0; g_deg[i] = 1.0f; }
        return;
    }
    int idx = (blockIdx.x - NPART) * 256 + threadIdx.x;   // 3*8192 pairs
    if (idx >= 3 * 8192) return;
    int m  = idx >> 13;
    int p  = idx & 8191;
    int n  = p >> 6;
    int k  = (p & 63) * 2;
    float f0, f1;
    if (m == 0) {
        f0 = (n < 64) ? Wp1[n * 256 + k]     : Wp1[(n - 64) * 256 + 128 + k];
        f1 = (n < 64) ? Wp1[n * 256 + k + 1] : Wp1[(n - 64) * 256 + 128 + k + 1];
    } else if (m == 1) { f0 = W1[n * 128 + k]; f1 = W1[n * 128 + k + 1]; }
    else               { f0 = W2[n * 128 + k]; f1 = W2[n * 128 + k + 1]; }
    split2(f0, f1, g_Bhi[m][p], g_Blo[m][p]);
}

#define RS 68

// ---------------- fused GEMM1+2: both tables from one x pass, 512 threads -----
// ABh = fp16(x @ Bp^T), xlh = fp16(x @ B1^T). 32-row tiles, 2-deep pipeline.
// smem words: St0 4096 | St1 4096 | Ah 2176 | Al 2176 | Bh 17408 | Bl 17408
__global__ void __launch_bounds__(512, 1)
gemm12(const float* __restrict__ X,
       const unsigned* __restrict__ Bhi, const unsigned* __restrict__ Blo,
       __half* __restrict__ Y0, __half* __restrict__ Y1, int M) {
    extern __shared__ unsigned sm[];
    float*    St0 = (float*)sm;
    float*    St1 = (float*)(sm + 4096);
    unsigned* Ah  = sm + 8192;
    unsigned* Al  = sm + 10368;
    unsigned* Bh  = sm + 12544;
    unsigned* Bl  = sm + 29952;
    const uint32_t st0b = smem_u32(St0);
    const uint32_t st1b = smem_u32(St1);

    const int tid  = threadIdx.x;
    const int lane = tid & 31;
    const int warp = tid >> 5;       // 0..15
    const int wm = warp & 1;         // 2 m-groups of 16 rows
    const int wn = warp >> 1;        // 8 n-groups of 16 cols
    const int g  = lane >> 2;
    const int tg = lane & 3;

    const int ntiles = (M + 31) >> 5;

    auto issue = [&](int tile, uint32_t stb) {
        int row0 = tile << 5;
        #pragma unroll
        for (int k = 0; k < 2; k++) {
            int idx = tid + k * 512;          // 1024 16B chunks
            int r = idx >> 5, c4 = idx & 31;
            int gr = row0 + r;
            cp_async16(stb + idx * 16,
                       X + (size_t)gr * 128 + c4 * 4, (gr < M) ? 16 : 0);
        }
        cp_commit();
    };

    int t0 = blockIdx.x;
    int t1 = t0 + gridDim.x;
    if (t0 < ntiles) issue(t0, st0b); else cp_commit();
    if (t1 < ntiles) issue(t1, st1b); else cp_commit();

    // stage both weight mats (hi+lo): 16384 pairs
    #pragma unroll 4
    for (int i = tid; i < 16384; i += 512) {
        int m = i >> 13;
        int p = i & 8191;
        int n = p >> 6, cp = p & 63;
        Bh[m * 8704 + n * RS + cp] = Bhi[i];
        Bl[m * 8704 + n * RS + cp] = Blo[i];
    }

    int pp = 0;
    for (int tile = t0; tile < ntiles; tile += gridDim.x) {
        cp_wait1();
        __syncthreads();     // stage full; prev iter's Ah/Al reads done
        float* St = pp ? St1 : St0;

        // convert stage -> Ah/Al
        #pragma unroll
        for (int k = 0; k < 4; k++) {
            int idx = tid + k * 512;        // 2048 float2 units
            int r = idx >> 6, cp = idx & 63;
            float2 f = *(const float2*)&St[idx * 2];
            split2(f.x, f.y, Ah[r * RS + cp], Al[r * RS + cp]);
        }
        __syncthreads();     // Ah/Al ready; stage reads done

        int nx = tile + 2 * gridDim.x;
        if (nx < ntiles) issue(nx, pp ? st1b : st0b); else cp_commit();

        // fragments once, two weight mats
        unsigned ahf[8][4], alf[8][4];
        #pragma unroll
        for (int kc = 0; kc < 8; kc++) {
            int w0 = (wm * 16 + g) * RS + kc * 8 + tg;
            ahf[kc][0] = Ah[w0];
            ahf[kc][1] = Ah[w0 + 8 * RS];
            ahf[kc][2] = Ah[w0 + 4];
            ahf[kc][3] = Ah[w0 + 8 * RS + 4];
            alf[kc][0] = Al[w0];
            alf[kc][1] = Al[w0 + 8 * RS];
            alf[kc][2] = Al[w0 + 4];
            alf[kc][3] = Al[w0 + 8 * RS + 4];
        }

        int r = (tile << 5) + wm * 16 + g;
        #pragma unroll
        for (int m = 0; m < 2; m++) {
            float acc[2][4];
            #pragma unroll
            for (int nt = 0; nt < 2; nt++)
                #pragma unroll
                for (int q = 0; q < 4; q++) acc[nt][q] = 0.f;
            #pragma unroll
            for (int kc = 0; kc < 8; kc++) {
                #pragma unroll
                for (int nt = 0; nt < 2; nt++) {
                    int nb = m * 8704 + (wn * 16 + nt * 8 + g) * RS + kc * 8 + tg;
                    unsigned bh0 = Bh[nb], bh1 = Bh[nb + 4];
                    unsigned bl0 = Bl[nb], bl1 = Bl[nb + 4];
                    mma_bf16(acc[nt], ahf[kc], bh0, bh1);
                    mma_bf16(acc[nt], ahf[kc], bl0, bl1);
                    mma_bf16(acc[nt], alf[kc], bh0, bh1);
                }
            }
            __half* Yh = m ? Y1 : Y0;
            #pragma unroll
            for (int nt = 0; nt < 2; nt++) {
                int c = wn * 16 + nt * 8 + tg * 2;
                if (r < M)
                    *(__half2*)&Yh[(size_t)r * 128 + c] =
                        __floats2half2_rn(acc[nt][0], acc[nt][1]);
                if (r + 8 < M)
                    *(__half2*)&Yh[(size_t)(r + 8) * 128 + c] =
                        __floats2half2_rn(acc[nt][2], acc[nt][3]);
            }
        }
        pp ^= 1;
    }
}

// ---------------- GEMM3 (R13 style): fp32 in, in-kernel convert ----------------
__global__ void __launch_bounds__(256, 2)
gemm_mma(const float* __restrict__ X, const unsigned* __restrict__ Bhi,
         const unsigned* __restrict__ Blo, __half* __restrict__ Yh, int M) {
    extern __shared__ unsigned sm[];
    float*    St = (float*)sm;                 // 4096 words
    unsigned* Ah = sm + 4096;
    unsigned* Al = sm + 4096 + 32 * RS;
    unsigned* Bh = sm + 4096 + 64 * RS;
    unsigned* Bl = sm + 4096 + 64 * RS + 128 * RS;
    const uint32_t st_base = smem_u32(St);

    const int tid  = threadIdx.x;
    const int lane = tid & 31;
    const int warp = tid >> 5;
    const int wm = warp & 1;
    const int wn = warp >> 1;
    const int g  = lane >> 2;
    const int tg = lane & 3;

    const int ntiles = (M + 31) >> 5;
    int tile = blockIdx.x;

    if (tile < ntiles) {
        #pragma unroll
        for (int k = 0; k < 4; k++) {
            int idx = tid + k * 256;
            int r = idx >> 5, c4 = idx & 31;
            int gr = (tile << 5) + r;
            cp_async16(st_base + idx * 16,
                       X + (size_t)gr * 128 + c4 * 4, (gr < M) ? 16 : 0);
        }
    }
    cp_commit();

    #pragma unroll 4
    for (int i = tid; i < 8192; i += 256) {
        int n = i >> 6, cp = i & 63;
        Bh[n * RS + cp] = Bhi[i];
        Bl[n * RS + cp] = Blo[i];
    }

    for (; tile < ntiles; tile += gridDim.x) {
        const int row0 = tile << 5;
        cp_wait0();
        __syncthreads();

        #pragma unroll
        for (int k = 0; k < 8; k++) {
            int idx = tid + k * 256;
            int r = idx >> 6, cp = idx & 63;
            float2 f = *(const float2*)&St[idx * 2];
            split2(f.x, f.y, Ah[r * RS + cp], Al[r * RS + cp]);
        }
        __syncthreads();

        int nxt = tile + gridDim.x;
        if (nxt < ntiles) {
            #pragma unroll
            for (int k = 0; k < 4; k++) {
                int idx = tid + k * 256;
                int r = idx >> 5, c4 = idx & 31;
                int gr = (nxt << 5) + r;
                cp_async16(st_base + idx * 16,
                           X + (size_t)gr * 128 + c4 * 4, (gr < M) ? 16 : 0);
            }
        }
        cp_commit();

        float acc[4][4];
        #pragma unroll
        for (int nt = 0; nt < 4; nt++)
            #pragma unroll
            for (int q = 0; q < 4; q++) acc[nt][q] = 0.f;

        #pragma unroll
        for (int kc = 0; kc < 8; kc++) {
            unsigned ah[4], al[4];
            int w0 = (wm * 16 + g) * RS + kc * 8 + tg;
            ah[0] = Ah[w0];
            ah[1] = Ah[w0 + 8 * RS];
            ah[2] = Ah[w0 + 4];
            ah[3] = Ah[w0 + 8 * RS + 4];
            al[0] = Al[w0];
            al[1] = Al[w0 + 8 * RS];
            al[2] = Al[w0 + 4];
            al[3] = Al[w0 + 8 * RS + 4];
            #pragma unroll
            for (int nt = 0; nt < 4; nt++) {
                int nb = (wn * 32 + nt * 8 + g) * RS + kc * 8 + tg;
                unsigned bh0 = Bh[nb], bh1 = Bh[nb + 4];
                unsigned bl0 = Bl[nb], bl1 = Bl[nb + 4];
                mma_bf16(acc[nt], ah, bh0, bh1);
                mma_bf16(acc[nt], ah, bl0, bl1);
                mma_bf16(acc[nt], al, bh0, bh1);
            }
        }

        int r = row0 + wm * 16 + g;
        #pragma unroll
        for (int nt = 0; nt < 4; nt++) {
            int c = wn * 32 + nt * 8 + tg * 2;
            if (r < M)
                *(__half2*)&Yh[(size_t)r * 128 + c] =
                    __floats2half2_rn(acc[nt][0], acc[nt][1]);
            if (r + 8 < M)
                *(__half2*)&Yh[(size_t)(r + 8) * 128 + c] =
                    __floats2half2_rn(acc[nt][2], acc[nt][3]);
        }
    }
}

// ---------------- edge conversion (dtype-robust) + dst histogram ----------------
__global__ void convert_edges(const int* __restrict__ raw) {
    bool is64 = true;
    #pragma unroll
    for (int i = 1; i < 128; i += 2)
        if (raw[i] != 0) { is64 = false; break; }
    int e = blockIdx.x * blockDim.x + threadIdx.x;
    if (e >= EE) return;
    int s, d;
    if (is64) { s = raw[2 * e];  d = raw[2 * (EE + e)]; }
    else      { s = raw[e];      d = raw[EE + e]; }
    g_src[e] = s;
    g_dst[e] = d;
    atomicAdd(&g_cnt[d], 1);
}

// ---------------- 3-kernel exclusive scan ----------------
__global__ void scan_part() {
    __shared__ int sm[256];
    int tid = threadIdx.x;
    int i = blockIdx.x * 256 + tid;
    sm[tid] = (i < NN) ? g_cnt[i] : 0;
    __syncthreads();
    for (int o = 128; o; o >>= 1) {
        if (tid < o) sm[tid] += sm[tid + o];
        __syncthreads();
    }
    if (tid == 0) g_part[blockIdx.x] = sm[0];
}

__global__ void scan_tops() {
    __shared__ int sm[256];
    int tid = threadIdx.x;
    int v = (tid < NPART) ? g_part[tid] : 0;
    sm[tid] = v;
    __syncthreads();
    for (int o = 1; o < 256; o <<= 1) {
        int t = sm[tid] + ((tid >= o) ? sm[tid - o] : 0);
        __syncthreads();
        sm[tid] = t;
        __syncthreads();
    }
    if (tid < NPART) g_part[tid] = sm[tid] - v;
}

__global__ void scan_final() {
    __shared__ int sm[256];
    int tid = threadIdx.x;
    int i = blockIdx.x * 256 + tid;
    int v = (i < NN) ? g_cnt[i] : 0;
    sm[tid] = v;
    __syncthreads();
    for (int o = 1; o < 256; o <<= 1) {
        int t = sm[tid] + ((tid >= o) ? sm[tid - o] : 0);
        __syncthreads();
        sm[tid] = t;
        __syncthreads();
    }
    if (i < NN) {
        int excl = sm[tid] - v + g_part[blockIdx.x];
        g_row[i] = excl;
        g_cur[i] = excl;
    }
    if (i == 0) g_row[NN] = EE;
}

// ------- fused edge pass: 2 edges per warp (16-lane halves) --------------------
__global__ void edge_fused(const float* __restrict__ b_p1,
                           const float* __restrict__ W_p2,
                           const float* __restrict__ b_p2) {
    int gw = (blockIdx.x * blockDim.x + threadIdx.x) >> 5;
    int lane = threadIdx.x & 31;
    int half = lane >> 4;
    int hl = lane & 15;
    int e = gw * 2 + half;
    if (e >= EE) return;
    int s = g_src[e];
    int d = g_dst[e];
    float4 a  = row4(g_ABh, s, hl * 4);
    uint2 ub  = *(const uint2*)&g_ABh[(size_t)d * 128 + 64 + hl * 4];
    float2 b01 = __half22float2(*(__half2*)&ub.x);
    float2 b23 = __half22float2(*(__half2*)&ub.y);
    float4 bp = *(const float4*)&b_p1[hl * 4];
    float4 w2 = *(const float4*)&W_p2[hl * 4];
    float h0 = fmaxf(a.x + b01.x + bp.x, 0.f);
    float h1 = fmaxf(a.y + b01.y + bp.y, 0.f);
    float h2 = fmaxf(a.z + b23.x + bp.z, 0.f);
    float h3 = fmaxf(a.w + b23.y + bp.w, 0.f);
    float p = h0 * w2.x + h1 * w2.y + h2 * w2.z + h3 * w2.w;
    #pragma unroll
    for (int o = 8; o; o >>= 1) p += __shfl_xor_sync(0xffffffffu, p, o);
    if (hl == 0) {
        float v = 1.f / (1.f + expf(-(p + b_p2[0])));
        int slot = atomicAdd(&g_cur[d], 1);
        g_csrc[slot] = s;
        g_cw[slot]   = v;
        atomicAdd(&g_deg[d], v);
    }
}

// ---------------- fused dinv + coef ----------------
__global__ void dinv_coef() {
    int n = blockIdx.x * blockDim.x + threadIdx.x;
    if (n >= NN) return;
    float dd = rsqrtf(g_deg[n]);
    g_dinv[n] = dd;
    int e0 = g_row[n], e1 = g_row[n + 1];
    for (int j = e0; j < e1; j++)
        g_cw[j] *= dd * rsqrtf(g_deg[g_csrc[j]]);
}

// ---------------- conv1: warp per node, 4x unroll, relu -> fp32 ----------------
__global__ void conv_relu(const float* __restrict__ bias) {
    int n = blockIdx.x * 8 + (threadIdx.x >> 5);
    int lane = threadIdx.x & 31;
    if (n >= NN) return;
    int f4 = lane * 4;
    float di = g_dinv[n];
    float c0 = di * di;
    float4 b4 = *(const float4*)&bias[f4];
    float4 x0 = row4(g_xlh, n, f4);
    float a0 = b4.x + c0 * x0.x;
    float a1 = b4.y + c0 * x0.y;
    float a2 = b4.z + c0 * x0.z;
    float a3 = b4.w + c0 * x0.w;
    int e0 = g_row[n], e1 = g_row[n + 1];
    int j = e0;
    for (; j + 4 <= e1; j += 4) {
        int s0 = g_csrc[j], s1 = g_csrc[j + 1], s2 = g_csrc[j + 2], s3 = g_csrc[j + 3];
        float w0 = g_cw[j], w1 = g_cw[j + 1], w2 = g_cw[j + 2], w3 = g_cw[j + 3];
        float4 r0 = row4(g_xlh, s0, f4);
        float4 r1 = row4(g_xlh, s1, f4);
        float4 r2 = row4(g_xlh, s2, f4);
        float4 r3 = row4(g_xlh, s3, f4);
        a0 += w0 * r0.x + w1 * r1.x + w2 * r2.x + w3 * r3.x;
        a1 += w0 * r0.y + w1 * r1.y + w2 * r2.y + w3 * r3.y;
        a2 += w0 * r0.z + w1 * r1.z + w2 * r2.z + w3 * r3.z;
        a3 += w0 * r0.w + w1 * r1.w + w2 * r2.w + w3 * r3.w;
    }
    for (; j < e1; j++) {
        int s = g_csrc[j];
        float w = g_cw[j];
        float4 r = row4(g_xlh, s, f4);
        a0 += w * r.x; a1 += w * r.y; a2 += w * r.z; a3 += w * r.w;
    }
    *(float4*)&g_x1[(size_t)n * 128 + f4] =
        make_float4(fmaxf(a0, 0.f), fmaxf(a1, 0.f), fmaxf(a2, 0.f), fmaxf(a3, 0.f));
}

// ---------------- conv2 + head: warp per node, shuffle reduction ----------------
__global__ void conv_head(const float* __restrict__ bias,
                          const float* __restrict__ W_lin,
                          const float* __restrict__ b_lin,
                          float* __restrict__ out) {
    int n = blockIdx.x * 8 + (threadIdx.x >> 5);
    int lane = threadIdx.x & 31;
    if (n >= NN) return;
    int f4 = lane * 4;
    float di = g_dinv[n];
    float c0 = di * di;
    float4 b4 = *(const float4*)&bias[f4];
    float4 x0 = row4(g_xlh, n, f4);
    float a0 = b4.x + c0 * x0.x;
    float a1 = b4.y + c0 * x0.y;
    float a2 = b4.z + c0 * x0.z;
    float a3 = b4.w + c0 * x0.w;
    int e0 = g_row[n], e1 = g_row[n + 1];
    int j = e0;
    for (; j + 4 <= e1; j += 4) {
        int s0 = g_csrc[j], s1 = g_csrc[j + 1], s2 = g_csrc[j + 2], s3 = g_csrc[j + 3];
        float w0 = g_cw[j], w1 = g_cw[j + 1], w2 = g_cw[j + 2], w3 = g_cw[j + 3];
        float4 r0 = row4(g_xlh, s0, f4);
        float4 r1 = row4(g_xlh, s1, f4);
        float4 r2 = row4(g_xlh, s2, f4);
        float4 r3 = row4(g_xlh, s3, f4);
        a0 += w0 * r0.x + w1 * r1.x + w2 * r2.x + w3 * r3.x;
        a1 += w0 * r0.y + w1 * r1.y + w2 * r2.y + w3 * r3.y;
        a2 += w0 * r0.z + w1 * r1.z + w2 * r2.z + w3 * r3.z;
        a3 += w0 * r0.w + w1 * r1.w + w2 * r2.w + w3 * r3.w;
    }
    for (; j < e1; j++) {
        int s = g_csrc[j];
        float w = g_cw[j];
        float4 r = row4(g_xlh, s, f4);
        a0 += w * r.x; a1 += w * r.y; a2 += w * r.z; a3 += w * r.w;
    }
    float v0 = fmaxf(a0, 0.f), v1 = fmaxf(a1, 0.f);
    float v2 = fmaxf(a2, 0.f), v3 = fmaxf(a3, 0.f);
    float4 wl0 = *(const float4*)&W_lin[f4];
    float4 wl1 = *(const float4*)&W_lin[128 + f4];
    float p0 = v0 * wl0.x + v1 * wl0.y + v2 * wl0.z + v3 * wl0.w;
    float p1 = v0 * wl1.x + v1 * wl1.y + v2 * wl1.z + v3 * wl1.w;
    #pragma unroll
    for (int o = 16; o; o >>= 1) {
        p0 += __shfl_xor_sync(0xffffffffu, p0, o);
        p1 += __shfl_xor_sync(0xffffffffu, p1, o);
    }
    if (lane == 0) {
        out[2 * n + 0] = 1.f / (1.f + expf(-(p0 + b_lin[0])));
        out[2 * n + 1] = 1.f / (1.f + expf(-(p1 + b_lin[1])));
    }
}

// ---------------- host ----------------
extern "C" void kernel_launch(void* const* d_in, const int* in_sizes, int n_in,
                              void* d_out, int out_size) {
    const float* x     = (const float*)d_in[0];
    const int*   ei    = (const int*)d_in[1];
    const float* W_p1  = (const float*)d_in[2];
    const float* b_p1  = (const float*)d_in[3];
    const float* W_p2  = (const float*)d_in[4];
    const float* b_p2  = (const float*)d_in[5];
    const float* W1    = (const float*)d_in[6];
    const float* b1    = (const float*)d_in[7];
    const float* W2    = (const float*)d_in[8];
    const float* b2    = (const float*)d_in[9];
    const float* W_lin = (const float*)d_in[10];
    const float* b_lin = (const float*)d_in[11];
    float* out = (float*)d_out;

    void *pABh, *pXLh, *pX1, *pBhi, *pBlo;
    cudaGetSymbolAddress(&pABh, g_ABh);
    cudaGetSymbolAddress(&pXLh, g_xlh);
    cudaGetSymbolAddress(&pX1,  g_x1);
    cudaGetSymbolAddress(&pBhi, g_Bhi);
    cudaGetSymbolAddress(&pBlo, g_Blo);
    const unsigned* Bhi = (const unsigned*)pBhi;
    const unsigned* Blo = (const unsigned*)pBlo;

    const int G12_SMEM = 47360 * 4;   // 189440 B -> 1 CTA/SM
    const int G3_SMEM  = 26112 * 4;   // 104448 B -> 2 CTAs/SM
    cudaFuncSetAttribute(gemm12,   cudaFuncAttributeMaxDynamicSharedMemorySize, G12_SMEM);
    cudaFuncSetAttribute(gemm_mma, cudaFuncAttributeMaxDynamicSharedMemorySize, G3_SMEM);

    const int edge_blocks = (EE / 2 + 7) / 8;
    const int e_blocks    = (EE + 255) / 256;
    const int n_blocks    = (NN + 255) / 256;
    const int conv_blocks = (NN + 7) / 8;

    init_misc<<<NPART + 96, 256>>>(W_p1, W1, W2);                         // 0
    convert_edges<<<e_blocks, 256>>>(ei);                                 // 1
    scan_part<<<NPART, 256>>>();                                          // 2
    gemm12<<<148, 512, G12_SMEM>>>(x, Bhi, Blo, (__half*)pABh,
                                   (__half*)pXLh, NN);                    // 3 (profiled)
    scan_tops<<<1, 256>>>();                                              // 4
    scan_final<<<NPART, 256>>>();                                         // 5
    edge_fused<<<edge_blocks, 256>>>(b_p1, W_p2, b_p2);                   // 6
    dinv_coef<<<n_blocks, 256>>>();                                       // 7
    conv_relu<<<conv_blocks, 256>>>(b1);                                  // 8
    gemm_mma<<<296, 256, G3_SMEM>>>((const float*)pX1, Bhi + 16384,
                                    Blo + 16384, (__half*)pXLh, NN);      // 9
    conv_head<<<conv_blocks, 256>>>(b2, W_lin, b_lin, out);               // 10
}

// round 17
// speedup vs baseline: 1.1443x; 1.0593x over previous
#include <cuda_runtime.h>
#include <cuda_bf16.h>
#include <cuda_fp16.h>
#include <cstdint>

#define NN 50000
#define EE 600000
#define NPART 196   // ceil(NN/256)

// ---------------- device scratch ----------------
__device__ __align__(16) float  g_deg[NN];
__device__ __align__(16) __half g_ABh[NN * 128];   // edge-MLP table (fp16)
__device__ __align__(16) __half g_xlh[NN * 128];   // conv message table (fp16)
__device__ __align__(16) float  g_x1[NN * 128];    // conv1 output (fp32)
__device__ __align__(16) int    g_src[EE];
__device__ __align__(16) int    g_dst[EE];
__device__ __align__(16) int    g_cnt[NN];
__device__ __align__(16) int    g_part[256];
__device__ __align__(16) int    g_row[NN + 1];
__device__ __align__(16) int    g_cur[NN];
__device__ __align__(16) int    g_csrc[EE];
__device__ __align__(16) float  g_cw[EE];
// bf16 hi/lo weights, row-major packed bf16x2: [mat][n*64 + colpair]
__device__ __align__(16) unsigned g_Bhi[3][8192];
__device__ __align__(16) unsigned g_Blo[3][8192];

// ---------------- PTX helpers (base PTX only) ----------------
__device__ __forceinline__ void mma_bf16(float* c, const unsigned* a,
                                         unsigned b0, unsigned b1) {
    asm volatile(
        "mma.sync.aligned.m16n8k16.row.col.f32.bf16.bf16.f32 "
        "{%0,%1,%2,%3}, {%4,%5,%6,%7}, {%8,%9}, {%0,%1,%2,%3};"
        : "+f"(c[0]), "+f"(c[1]), "+f"(c[2]), "+f"(c[3])
        : "r"(a[0]), "r"(a[1]), "r"(a[2]), "r"(a[3]), "r"(b0), "r"(b1));
}
__device__ __forceinline__ void ldsm4(unsigned* r, uint32_t addr) {
    asm volatile("ldmatrix.sync.aligned.m8n8.x4.shared.b16 {%0,%1,%2,%3}, [%4];"
                 : "=r"(r[0]), "=r"(r[1]), "=r"(r[2]), "=r"(r[3]) : "r"(addr));
}
__device__ __forceinline__ uint32_t smem_u32(const void* p) {
    uint32_t a;
    asm("{ .reg .u64 t; cvta.to.shared.u64 t, %1; cvt.u32.u64 %0, t; }"
        : "=r"(a) : "l"(p));
    return a;
}
__device__ __forceinline__ void cp_async16(uint32_t dst, const void* src, int nbytes) {
    asm volatile("cp.async.cg.shared.global [%0], [%1], 16, %2;"
                 :: "r"(dst), "l"(src), "r"(nbytes) : "memory");
}
__device__ __forceinline__ void cp_commit() {
    asm volatile("cp.async.commit_group;" ::: "memory");
}
__device__ __forceinline__ void cp_wait0() {
    asm volatile("cp.async.wait_group 0;" ::: "memory");
}
__device__ __forceinline__ void cp_wait1() {
    asm volatile("cp.async.wait_group 1;" ::: "memory");
}
// gather 4 features from a fp16 table row
__device__ __forceinline__ float4 row4(const __half* tab, int s, int f4) {
    uint2 u = *(const uint2*)&tab[(size_t)s * 128 + f4];
    float2 f01 = __half22float2(*(__half2*)&u.x);
    float2 f23 = __half22float2(*(__half2*)&u.y);
    return make_float4(f01.x, f01.y, f23.x, f23.y);
}
__device__ __forceinline__ void split2(float f0, float f1, unsigned& uh, unsigned& ul) {
    __nv_bfloat162 h = __floats2bfloat162_rn(f0, f1);
    __nv_bfloat162 l = __floats2bfloat162_rn(f0 - __bfloat162float(h.x),
                                             f1 - __bfloat162float(h.y));
    uh = *(unsigned*)&h;
    ul = *(unsigned*)&l;
}

// ---------------- init: zero cnt, deg=1, split-bf16 weights ----------------
__global__ void init_misc(const float* __restrict__ Wp1,
                          const float* __restrict__ W1,
                          const float* __restrict__ W2) {
    if (blockIdx.x < NPART) {
        int i = blockIdx.x * 256 + threadIdx.x;
        if (i < NN) { g_cnt[i] = 0; g_deg[i] = 1.0f; }
        return;
    }
    int idx = (blockIdx.x - NPART) * 256 + threadIdx.x;   // 3*8192 pairs
    if (idx >= 3 * 8192) return;
    int m  = idx >> 13;
    int p  = idx & 8191;
    int n  = p >> 6;
    int k  = (p & 63) * 2;
    float f0, f1;
    if (m == 0) {
        f0 = (n < 64) ? Wp1[n * 256 + k]     : Wp1[(n - 64) * 256 + 128 + k];
        f1 = (n < 64) ? Wp1[n * 256 + k + 1] : Wp1[(n - 64) * 256 + 128 + k + 1];
    } else if (m == 1) { f0 = W1[n * 128 + k]; f1 = W1[n * 128 + k + 1]; }
    else               { f0 = W2[n * 128 + k]; f1 = W2[n * 128 + k + 1]; }
    split2(f0, f1, g_Bhi[m][p], g_Blo[m][p]);
}

#define RS 68

// ---------------- fused GEMM1+2, ldmatrix fragments, 512 threads ----------------
// smem words: St0 4096 | St1 4096 | Ah 2176 | Al 2176 | Bh 17408 | Bl 17408
__global__ void __launch_bounds__(512, 1)
gemm12(const float* __restrict__ X,
       const unsigned* __restrict__ Bhi, const unsigned* __restrict__ Blo,
       __half* __restrict__ Y0, __half* __restrict__ Y1, int M) {
    extern __shared__ unsigned sm[];
    float*    St0 = (float*)sm;
    float*    St1 = (float*)(sm + 4096);
    unsigned* Ah  = sm + 8192;
    unsigned* Al  = sm + 10368;
    unsigned* Bh  = sm + 12544;
    unsigned* Bl  = sm + 29952;
    const uint32_t st0b = smem_u32(St0);
    const uint32_t st1b = smem_u32(St1);

    const int tid  = threadIdx.x;
    const int lane = tid & 31;
    const int warp = tid >> 5;       // 0..15
    const int wm = warp & 1;         // 2 m-groups of 16 rows
    const int wn = warp >> 1;        // 8 n-groups of 16 cols
    const int g  = lane >> 2;
    const int tg = lane & 3;
    const int sub = lane >> 3, lr = lane & 7;

    // ldmatrix lane addresses (bytes)
    const uint32_t aoff = ((wm * 16 + (sub & 1) * 8 + lr) * RS + (sub >> 1) * 4) * 4;
    const uint32_t ah_b = smem_u32(Ah) + aoff;
    const uint32_t al_b = smem_u32(Al) + aoff;
    const uint32_t boff = ((wn * 16 + (sub >> 1) * 8 + lr) * RS + (sub & 1) * 4) * 4;
    const uint32_t bh_b = smem_u32(Bh) + boff;
    const uint32_t bl_b = smem_u32(Bl) + boff;

    const int ntiles = (M + 31) >> 5;

    auto issue = [&](int tile, uint32_t stb) {
        int row0 = tile << 5;
        #pragma unroll
        for (int k = 0; k < 2; k++) {
            int idx = tid + k * 512;
            int r = idx >> 5, c4 = idx & 31;
            int gr = row0 + r;
            cp_async16(stb + idx * 16,
                       X + (size_t)gr * 128 + c4 * 4, (gr < M) ? 16 : 0);
        }
        cp_commit();
    };

    int t0 = blockIdx.x;
    int t1 = t0 + gridDim.x;
    if (t0 < ntiles) issue(t0, st0b); else cp_commit();
    if (t1 < ntiles) issue(t1, st1b); else cp_commit();

    // stage both weight mats (hi+lo): 16384 pairs
    #pragma unroll 4
    for (int i = tid; i < 16384; i += 512) {
        int m = i >> 13;
        int p = i & 8191;
        int n = p >> 6, cp = p & 63;
        Bh[m * 8704 + n * RS + cp] = Bhi[i];
        Bl[m * 8704 + n * RS + cp] = Blo[i];
    }

    int pp = 0;
    for (int tile = t0; tile < ntiles; tile += gridDim.x) {
        cp_wait1();
        __syncthreads();
        float* St = pp ? St1 : St0;

        #pragma unroll
        for (int k = 0; k < 4; k++) {
            int idx = tid + k * 512;
            int r = idx >> 6, cp = idx & 63;
            float2 f = *(const float2*)&St[idx * 2];
            split2(f.x, f.y, Ah[r * RS + cp], Al[r * RS + cp]);
        }
        __syncthreads();

        int nx = tile + 2 * gridDim.x;
        if (nx < ntiles) issue(nx, pp ? st1b : st0b); else cp_commit();

        unsigned ahf[8][4], alf[8][4];
        #pragma unroll
        for (int kc = 0; kc < 8; kc++) {
            ldsm4(ahf[kc], ah_b + kc * 32);
            ldsm4(alf[kc], al_b + kc * 32);
        }

        int r = (tile << 5) + wm * 16 + g;
        #pragma unroll
        for (int m = 0; m < 2; m++) {
            float acc[2][4];
            #pragma unroll
            for (int nt = 0; nt < 2; nt++)
                #pragma unroll
                for (int q = 0; q < 4; q++) acc[nt][q] = 0.f;
            #pragma unroll
            for (int kc = 0; kc < 8; kc++) {
                unsigned bh4[4], bl4[4];
                ldsm4(bh4, bh_b + m * 8704 * 4 + kc * 32);
                ldsm4(bl4, bl_b + m * 8704 * 4 + kc * 32);
                mma_bf16(acc[0], ahf[kc], bh4[0], bh4[1]);
                mma_bf16(acc[0], ahf[kc], bl4[0], bl4[1]);
                mma_bf16(acc[0], alf[kc], bh4[0], bh4[1]);
                mma_bf16(acc[1], ahf[kc], bh4[2], bh4[3]);
                mma_bf16(acc[1], ahf[kc], bl4[2], bl4[3]);
                mma_bf16(acc[1], alf[kc], bh4[2], bh4[3]);
            }
            __half* Yh = m ? Y1 : Y0;
            #pragma unroll
            for (int nt = 0; nt < 2; nt++) {
                int c = wn * 16 + nt * 8 + tg * 2;
                if (r < M)
                    *(__half2*)&Yh[(size_t)r * 128 + c] =
                        __floats2half2_rn(acc[nt][0], acc[nt][1]);
                if (r + 8 < M)
                    *(__half2*)&Yh[(size_t)(r + 8) * 128 + c] =
                        __floats2half2_rn(acc[nt][2], acc[nt][3]);
            }
        }
        pp ^= 1;
    }
}

// ---------------- GEMM3: fp32 in, in-kernel convert, ldmatrix ----------------
__global__ void __launch_bounds__(256, 2)
gemm_mma(const float* __restrict__ X, const unsigned* __restrict__ Bhi,
         const unsigned* __restrict__ Blo, __half* __restrict__ Yh, int M) {
    extern __shared__ unsigned sm[];
    float*    St = (float*)sm;                 // 4096 words
    unsigned* Ah = sm + 4096;
    unsigned* Al = sm + 4096 + 32 * RS;
    unsigned* Bh = sm + 4096 + 64 * RS;
    unsigned* Bl = sm + 4096 + 64 * RS + 128 * RS;
    const uint32_t st_base = smem_u32(St);

    const int tid  = threadIdx.x;
    const int lane = tid & 31;
    const int warp = tid >> 5;
    const int wm = warp & 1;
    const int wn = warp >> 1;    // 4 n-groups of 32 cols
    const int g  = lane >> 2;
    const int tg = lane & 3;
    const int sub = lane >> 3, lr = lane & 7;

    const uint32_t aoff = ((wm * 16 + (sub & 1) * 8 + lr) * RS + (sub >> 1) * 4) * 4;
    const uint32_t ah_b = smem_u32(Ah) + aoff;
    const uint32_t al_b = smem_u32(Al) + aoff;
    const uint32_t boff = ((wn * 32 + (sub >> 1) * 8 + lr) * RS + (sub & 1) * 4) * 4;
    const uint32_t bh_b = smem_u32(Bh) + boff;
    const uint32_t bl_b = smem_u32(Bl) + boff;
    const uint32_t colstep = 16 * RS * 4;      // +16 cols

    const int ntiles = (M + 31) >> 5;
    int tile = blockIdx.x;

    if (tile < ntiles) {
        #pragma unroll
        for (int k = 0; k < 4; k++) {
            int idx = tid + k * 256;
            int r = idx >> 5, c4 = idx & 31;
            int gr = (tile << 5) + r;
            cp_async16(st_base + idx * 16,
                       X + (size_t)gr * 128 + c4 * 4, (gr < M) ? 16 : 0);
        }
    }
    cp_commit();

    #pragma unroll 4
    for (int i = tid; i < 8192; i += 256) {
        int n = i >> 6, cp = i & 63;
        Bh[n * RS + cp] = Bhi[i];
        Bl[n * RS + cp] = Blo[i];
    }

    for (; tile < ntiles; tile += gridDim.x) {
        const int row0 = tile << 5;
        cp_wait0();
        __syncthreads();

        #pragma unroll
        for (int k = 0; k < 8; k++) {
            int idx = tid + k * 256;
            int r = idx >> 6, cp = idx & 63;
            float2 f = *(const float2*)&St[idx * 2];
            split2(f.x, f.y, Ah[r * RS + cp], Al[r * RS + cp]);
        }
        __syncthreads();

        int nxt = tile + gridDim.x;
        if (nxt < ntiles) {
            #pragma unroll
            for (int k = 0; k < 4; k++) {
                int idx = tid + k * 256;
                int r = idx >> 5, c4 = idx & 31;
                int gr = (nxt << 5) + r;
                cp_async16(st_base + idx * 16,
                           X + (size_t)gr * 128 + c4 * 4, (gr < M) ? 16 : 0);
            }
        }
        cp_commit();

        float acc[4][4];
        #pragma unroll
        for (int nt = 0; nt < 4; nt++)
            #pragma unroll
            for (int q = 0; q < 4; q++) acc[nt][q] = 0.f;

        #pragma unroll
        for (int kc = 0; kc < 8; kc++) {
            unsigned ah[4], al[4], bh0[4], bh1[4], bl0[4], bl1[4];
            ldsm4(ah, ah_b + kc * 32);
            ldsm4(al, al_b + kc * 32);
            ldsm4(bh0, bh_b + kc * 32);
            ldsm4(bh1, bh_b + colstep + kc * 32);
            ldsm4(bl0, bl_b + kc * 32);
            ldsm4(bl1, bl_b + colstep + kc * 32);
            mma_bf16(acc[0], ah, bh0[0], bh0[1]);
            mma_bf16(acc[0], ah, bl0[0], bl0[1]);
            mma_bf16(acc[0], al, bh0[0], bh0[1]);
            mma_bf16(acc[1], ah, bh0[2], bh0[3]);
            mma_bf16(acc[1], ah, bl0[2], bl0[3]);
            mma_bf16(acc[1], al, bh0[2], bh0[3]);
            mma_bf16(acc[2], ah, bh1[0], bh1[1]);
            mma_bf16(acc[2], ah, bl1[0], bl1[1]);
            mma_bf16(acc[2], al, bh1[0], bh1[1]);
            mma_bf16(acc[3], ah, bh1[2], bh1[3]);
            mma_bf16(acc[3], ah, bl1[2], bl1[3]);
            mma_bf16(acc[3], al, bh1[2], bh1[3]);
        }

        int r = row0 + wm * 16 + g;
        #pragma unroll
        for (int nt = 0; nt < 4; nt++) {
            int c = wn * 32 + nt * 8 + tg * 2;
            if (r < M)
                *(__half2*)&Yh[(size_t)r * 128 + c] =
                    __floats2half2_rn(acc[nt][0], acc[nt][1]);
            if (r + 8 < M)
                *(__half2*)&Yh[(size_t)(r + 8) * 128 + c] =
                    __floats2half2_rn(acc[nt][2], acc[nt][3]);
        }
    }
}

// ---------------- edge conversion (dtype-robust) + dst histogram ----------------
__global__ void convert_edges(const int* __restrict__ raw) {
    bool is64 = true;
    #pragma unroll
    for (int i = 1; i < 128; i += 2)
        if (raw[i] != 0) { is64 = false; break; }
    int e = blockIdx.x * blockDim.x + threadIdx.x;
    if (e >= EE) return;
    int s, d;
    if (is64) { s = raw[2 * e];  d = raw[2 * (EE + e)]; }
    else      { s = raw[e];      d = raw[EE + e]; }
    g_src[e] = s;
    g_dst[e] = d;
    atomicAdd(&g_cnt[d], 1);
}

// ---------------- 2-kernel exclusive scan ----------------
__global__ void scan_part() {
    __shared__ int sm[256];
    int tid = threadIdx.x;
    int i = blockIdx.x * 256 + tid;
    sm[tid] = (i < NN) ? g_cnt[i] : 0;
    __syncthreads();
    for (int o = 128; o; o >>= 1) {
        if (tid < o) sm[tid] += sm[tid + o];
        __syncthreads();
    }
    if (tid == 0) g_part[blockIdx.x] = sm[0];
}

// merged tops+final: every block re-scans the 196 partials locally
__global__ void scan_final2() {
    __shared__ int top[256];
    __shared__ int sm[256];
    int tid = threadIdx.x;
    top[tid] = (tid < NPART) ? g_part[tid] : 0;
    __syncthreads();
    for (int o = 1; o < 256; o <<= 1) {
        int t = top[tid] + ((tid >= o) ? top[tid - o] : 0);
        __syncthreads();
        top[tid] = t;
        __syncthreads();
    }
    int base = (blockIdx.x > 0) ? top[blockIdx.x - 1] : 0;   // exclusive block base

    int i = blockIdx.x * 256 + tid;
    int v = (i < NN) ? g_cnt[i] : 0;
    sm[tid] = v;
    __syncthreads();
    for (int o = 1; o < 256; o <<= 1) {
        int t = sm[tid] + ((tid >= o) ? sm[tid - o] : 0);
        __syncthreads();
        sm[tid] = t;
        __syncthreads();
    }
    if (i < NN) {
        int excl = sm[tid] - v + base;
        g_row[i] = excl;
        g_cur[i] = excl;
    }
    if (i == 0) g_row[NN] = EE;
}

// ------- fused edge pass: 2 edges per warp (16-lane halves) --------------------
__global__ void edge_fused(const float* __restrict__ b_p1,
                           const float* __restrict__ W_p2,
                           const float* __restrict__ b_p2) {
    int gw = (blockIdx.x * blockDim.x + threadIdx.x) >> 5;
    int lane = threadIdx.x & 31;
    int half = lane >> 4;
    int hl = lane & 15;
    int e = gw * 2 + half;
    if (e >= EE) return;
    int s = g_src[e];
    int d = g_dst[e];
    float4 a  = row4(g_ABh, s, hl * 4);
    uint2 ub  = *(const uint2*)&g_ABh[(size_t)d * 128 + 64 + hl * 4];
    float2 b01 = __half22float2(*(__half2*)&ub.x);
    float2 b23 = __half22float2(*(__half2*)&ub.y);
    float4 bp = *(const float4*)&b_p1[hl * 4];
    float4 w2 = *(const float4*)&W_p2[hl * 4];
    float h0 = fmaxf(a.x + b01.x + bp.x, 0.f);
    float h1 = fmaxf(a.y + b01.y + bp.y, 0.f);
    float h2 = fmaxf(a.z + b23.x + bp.z, 0.f);
    float h3 = fmaxf(a.w + b23.y + bp.w, 0.f);
    float p = h0 * w2.x + h1 * w2.y + h2 * w2.z + h3 * w2.w;
    #pragma unroll
    for (int o = 8; o; o >>= 1) p += __shfl_xor_sync(0xffffffffu, p, o);
    if (hl == 0) {
        float v = 1.f / (1.f + expf(-(p + b_p2[0])));
        int slot = atomicAdd(&g_cur[d], 1);
        g_csrc[slot] = s;
        g_cw[slot]   = v;
        atomicAdd(&g_deg[d], v);
    }
}

// ---------------- conv1: warp per node, normalization fused ----------------
__global__ void conv_relu(const float* __restrict__ bias) {
    int n = blockIdx.x * 8 + (threadIdx.x >> 5);
    int lane = threadIdx.x & 31;
    if (n >= NN) return;
    int f4 = lane * 4;
    float dd = rsqrtf(g_deg[n]);
    float c0 = dd * dd;
    float4 b4 = *(const float4*)&bias[f4];
    float4 x0 = row4(g_xlh, n, f4);
    float a0 = b4.x + c0 * x0.x;
    float a1 = b4.y + c0 * x0.y;
    float a2 = b4.z + c0 * x0.z;
    float a3 = b4.w + c0 * x0.w;
    int e0 = g_row[n], e1 = g_row[n + 1];
    int j = e0;
    for (; j + 4 <= e1; j += 4) {
        int s0 = g_csrc[j], s1 = g_csrc[j + 1], s2 = g_csrc[j + 2], s3 = g_csrc[j + 3];
        float w0 = g_cw[j]     * rsqrtf(g_deg[s0]) * dd;
        float w1 = g_cw[j + 1] * rsqrtf(g_deg[s1]) * dd;
        float w2 = g_cw[j + 2] * rsqrtf(g_deg[s2]) * dd;
        float w3 = g_cw[j + 3] * rsqrtf(g_deg[s3]) * dd;
        float4 r0 = row4(g_xlh, s0, f4);
        float4 r1 = row4(g_xlh, s1, f4);
        float4 r2 = row4(g_xlh, s2, f4);
        float4 r3 = row4(g_xlh, s3, f4);
        a0 += w0 * r0.x + w1 * r1.x + w2 * r2.x + w3 * r3.x;
        a1 += w0 * r0.y + w1 * r1.y + w2 * r2.y + w3 * r3.y;
        a2 += w0 * r0.z + w1 * r1.z + w2 * r2.z + w3 * r3.z;
        a3 += w0 * r0.w + w1 * r1.w + w2 * r2.w + w3 * r3.w;
    }
    for (; j < e1; j++) {
        int s = g_csrc[j];
        float w = g_cw[j] * rsqrtf(g_deg[s]) * dd;
        float4 r = row4(g_xlh, s, f4);
        a0 += w * r.x; a1 += w * r.y; a2 += w * r.z; a3 += w * r.w;
    }
    *(float4*)&g_x1[(size_t)n * 128 + f4] =
        make_float4(fmaxf(a0, 0.f), fmaxf(a1, 0.f), fmaxf(a2, 0.f), fmaxf(a3, 0.f));
}

// ---------------- conv2 + head: warp per node, normalization fused -------------
__global__ void conv_head(const float* __restrict__ bias,
                          const float* __restrict__ W_lin,
                          const float* __restrict__ b_lin,
                          float* __restrict__ out) {
    int n = blockIdx.x * 8 + (threadIdx.x >> 5);
    int lane = threadIdx.x & 31;
    if (n >= NN) return;
    int f4 = lane * 4;
    float dd = rsqrtf(g_deg[n]);
    float c0 = dd * dd;
    float4 b4 = *(const float4*)&bias[f4];
    float4 x0 = row4(g_xlh, n, f4);
    float a0 = b4.x + c0 * x0.x;
    float a1 = b4.y + c0 * x0.y;
    float a2 = b4.z + c0 * x0.z;
    float a3 = b4.w + c0 * x0.w;
    int e0 = g_row[n], e1 = g_row[n + 1];
    int j = e0;
    for (; j + 4 <= e1; j += 4) {
        int s0 = g_csrc[j], s1 = g_csrc[j + 1], s2 = g_csrc[j + 2], s3 = g_csrc[j + 3];
        float w0 = g_cw[j]     * rsqrtf(g_deg[s0]) * dd;
        float w1 = g_cw[j + 1] * rsqrtf(g_deg[s1]) * dd;
        float w2 = g_cw[j + 2] * rsqrtf(g_deg[s2]) * dd;
        float w3 = g_cw[j + 3] * rsqrtf(g_deg[s3]) * dd;
        float4 r0 = row4(g_xlh, s0, f4);
        float4 r1 = row4(g_xlh, s1, f4);
        float4 r2 = row4(g_xlh, s2, f4);
        float4 r3 = row4(g_xlh, s3, f4);
        a0 += w0 * r0.x + w1 * r1.x + w2 * r2.x + w3 * r3.x;
        a1 += w0 * r0.y + w1 * r1.y + w2 * r2.y + w3 * r3.y;
        a2 += w0 * r0.z + w1 * r1.z + w2 * r2.z + w3 * r3.z;
        a3 += w0 * r0.w + w1 * r1.w + w2 * r2.w + w3 * r3.w;
    }
    for (; j < e1; j++) {
        int s = g_csrc[j];
        float w = g_cw[j] * rsqrtf(g_deg[s]) * dd;
        float4 r = row4(g_xlh, s, f4);
        a0 += w * r.x; a1 += w * r.y; a2 += w * r.z; a3 += w * r.w;
    }
    float v0 = fmaxf(a0, 0.f), v1 = fmaxf(a1, 0.f);
    float v2 = fmaxf(a2, 0.f), v3 = fmaxf(a3, 0.f);
    float4 wl0 = *(const float4*)&W_lin[f4];
    float4 wl1 = *(const float4*)&W_lin[128 + f4];
    float p0 = v0 * wl0.x + v1 * wl0.y + v2 * wl0.z + v3 * wl0.w;
    float p1 = v0 * wl1.x + v1 * wl1.y + v2 * wl1.z + v3 * wl1.w;
    #pragma unroll
    for (int o = 16; o; o >>= 1) {
        p0 += __shfl_xor_sync(0xffffffffu, p0, o);
        p1 += __shfl_xor_sync(0xffffffffu, p1, o);
    }
    if (lane == 0) {
        out[2 * n + 0] = 1.f / (1.f + expf(-(p0 + b_lin[0])));
        out[2 * n + 1] = 1.f / (1.f + expf(-(p1 + b_lin[1])));
    }
}

// ---------------- host ----------------
extern "C" void kernel_launch(void* const* d_in, const int* in_sizes, int n_in,
                              void* d_out, int out_size) {
    const float* x     = (const float*)d_in[0];
    const int*   ei    = (const int*)d_in[1];
    const float* W_p1  = (const float*)d_in[2];
    const float* b_p1  = (const float*)d_in[3];
    const float* W_p2  = (const float*)d_in[4];
    const float* b_p2  = (const float*)d_in[5];
    const float* W1    = (const float*)d_in[6];
    const float* b1    = (const float*)d_in[7];
    const float* W2    = (const float*)d_in[8];
    const float* b2    = (const float*)d_in[9];
    const float* W_lin = (const float*)d_in[10];
    const float* b_lin = (const float*)d_in[11];
    float* out = (float*)d_out;

    void *pABh, *pXLh, *pX1, *pBhi, *pBlo;
    cudaGetSymbolAddress(&pABh, g_ABh);
    cudaGetSymbolAddress(&pXLh, g_xlh);
    cudaGetSymbolAddress(&pX1,  g_x1);
    cudaGetSymbolAddress(&pBhi, g_Bhi);
    cudaGetSymbolAddress(&pBlo, g_Blo);
    const unsigned* Bhi = (const unsigned*)pBhi;
    const unsigned* Blo = (const unsigned*)pBlo;

    const int G12_SMEM = 47360 * 4;   // 189440 B -> 1 CTA/SM
    const int G3_SMEM  = 26112 * 4;   // 104448 B -> 2 CTAs/SM
    cudaFuncSetAttribute(gemm12,   cudaFuncAttributeMaxDynamicSharedMemorySize, G12_SMEM);
    cudaFuncSetAttribute(gemm_mma, cudaFuncAttributeMaxDynamicSharedMemorySize, G3_SMEM);

    const int edge_blocks = (EE / 2 + 7) / 8;
    const int e_blocks    = (EE + 255) / 256;
    const int conv_blocks = (NN + 7) / 8;

    init_misc<<<NPART + 96, 256>>>(W_p1, W1, W2);                         // 0
    convert_edges<<<e_blocks, 256>>>(ei);                                 // 1
    scan_part<<<NPART, 256>>>();                                          // 2
    gemm12<<<148, 512, G12_SMEM>>>(x, Bhi, Blo, (__half*)pABh,
                                   (__half*)pXLh, NN);                    // 3 (profiled)
    scan_final2<<<NPART, 256>>>();                                        // 4
    edge_fused<<<edge_blocks, 256>>>(b_p1, W_p2, b_p2);                   // 5
    conv_relu<<<conv_blocks, 256>>>(b1);                                  // 6
    gemm_mma<<<296, 256, G3_SMEM>>>((const float*)pX1, Bhi + 16384,
                                    Blo + 16384, (__half*)pXLh, NN);      // 7
    conv_head<<<conv_blocks, 256>>>(b2, W_lin, b_lin, out);               // 8
}